// round 10
// baseline (speedup 1.0000x reference)
#include <cuda_runtime.h>
#include <cuda_bf16.h>
#include <cstdint>

// Problem constants
#define B_    8
#define L_    2048
#define D_    64
#define TOPK_ 32

// Kernel A tiling
#define TQ     64                // query rows per block
#define CK     128               // keys per chunk
#define NCHUNK (L_ / CK)         // 16
#define NBLK   (B_ * L_ / TQ)    // 256
#define BPB    (L_ / TQ)         // 32

// Selection: analytic threshold tau = Z_TAU * ||q|| / 8
// count ~ Binomial(2048, P(Z>1.70)=.0446): E=91.3, sd=9.3
#define Z_TAU 1.70f
#define MINC  40                 // containment guard (P<2e-8/row)
#define CAP   144                // overflow guard  (P<1e-8/row)
#define CAPG  160                // global candidate stride

#define KST  72                  // Kbf smem row stride (bf16 elems)

// ---- kernel A dynamic smem layout (bytes) ----
#define OFF_KBF   0              // bf16 [2][128][72] = 36864
#define OFF_QS    36864          // f32  [64][68]     = 17408
#define OFF_TAU   54272          // f32  [64]         =   256
#define OFF_CNT   54528          // int  [64]         =   256
#define SMEM_A    54784          // x2 blocks/SM = 109568

// Global scratch
__device__ __nv_bfloat16 gKbf[(size_t)B_ * L_ * D_];      // 2 MB
__device__ int g_cnt[B_ * L_];
__device__ int g_cand[(size_t)B_ * L_ * CAPG];            // 10.5 MB

__device__ __forceinline__ unsigned f2sortable(float f) {
    unsigned bb = __float_as_uint(f);
    return (bb & 0x80000000u) ? ~bb : (bb | 0x80000000u);
}

__device__ __forceinline__ uint32_t pack_bf2(float lo, float hi) {
    __nv_bfloat162 h2 = __floats2bfloat162_rn(lo, hi);
    return *reinterpret_cast<uint32_t*>(&h2);
}

__device__ __forceinline__ void mma_bf16(
    float& c0, float& c1, float& c2, float& c3,
    uint32_t a0, uint32_t a1, uint32_t a2, uint32_t a3,
    uint32_t b0, uint32_t b1)
{
    asm volatile(
        "mma.sync.aligned.m16n8k16.row.col.f32.bf16.bf16.f32 "
        "{%0,%1,%2,%3}, {%4,%5,%6,%7}, {%8,%9}, {%0,%1,%2,%3};\n"
        : "+f"(c0), "+f"(c1), "+f"(c2), "+f"(c3)
        : "r"(a0), "r"(a1), "r"(a2), "r"(a3), "r"(b0), "r"(b1));
}

__device__ __forceinline__ void cp_async16(uint32_t smem_dst, const void* gsrc) {
    asm volatile("cp.async.cg.shared.global [%0], [%1], 16;\n"
                 :: "r"(smem_dst), "l"(gsrc));
}
__device__ __forceinline__ void cp_commit() {
    asm volatile("cp.async.commit_group;\n");
}
template <int N>
__device__ __forceinline__ void cp_wait() {
    asm volatile("cp.async.wait_group %0;\n" :: "n"(N));
}

// ---------------------------------------------------------------------------
// Kernel 0: K fp32 -> bf16
// ---------------------------------------------------------------------------
__global__ __launch_bounds__(256) void convert_k(const float* __restrict__ k) {
    int idx = blockIdx.x * 256 + threadIdx.x;
    float4 kv = *(const float4*)(k + (size_t)idx * 4);
    uint2 o;
    o.x = pack_bf2(kv.x, kv.y);
    o.y = pack_bf2(kv.z, kv.w);
    *(uint2*)((unsigned short*)gKbf + (size_t)idx * 4) = o;
}

// ---------------------------------------------------------------------------
// Kernel A: HMMA scores + analytic-threshold candidate harvest -> global
// TQ=64: warp w -> key-slice ns=w&3, row-half rh=w>>2 (rows rh*32..rh*32+31)
// B fragments loaded once per nt, reused across both 16-row tiles.
// ---------------------------------------------------------------------------
__global__ __launch_bounds__(256, 2) void score_harvest(
    const float* __restrict__ q)
{
    extern __shared__ __align__(16) char smem[];
    unsigned short* Kbf = (unsigned short*)(smem + OFF_KBF);
    float* Qs   = (float*)(smem + OFF_QS);
    float* tauA = (float*)(smem + OFF_TAU);
    int*   cnt  = (int*)(smem + OFF_CNT);

    const int t    = threadIdx.x;
    const int lane = t & 31;
    const int w    = t >> 5;
    const unsigned full = 0xffffffffu;

    const int rowBase = blockIdx.x * TQ;
    const int b       = blockIdx.x / BPB;
    const __nv_bfloat16* gkb = gKbf + (size_t)b * L_ * D_;
    const uint32_t ksBase = (uint32_t)__cvta_generic_to_shared(Kbf);

    for (int i = t; i < TQ * 16; i += 256) {
        int row = i >> 4, dg4 = (i & 15) << 2;
        *(float4*)(Qs + row * 68 + dg4) =
            *(const float4*)(q + ((size_t)(rowBase + row)) * D_ + dg4);
    }
    if (t < TQ) cnt[t] = 0;
    __syncthreads();

    // per-row analytic tau (warp w -> rows 8w..8w+7)
    for (int rr = 0; rr < 8; ++rr) {
        int row = w * 8 + rr;
        float x = Qs[row * 68 + lane], y = Qs[row * 68 + lane + 32];
        float nrm = x * x + y * y;
        #pragma unroll
        for (int o = 16; o >= 1; o >>= 1) nrm += __shfl_xor_sync(full, nrm, o);
        if (lane == 0) tauA[row] = Z_TAU * sqrtf(nrm) * 0.125f;
    }

    // A fragments (Q): 2 tiles of 16 rows per warp, loaded once
    const int rh = w >> 2;                 // row half (0/1)
    const int ns = w & 3;                  // 32-key slice
    const int ac = (lane & 3) * 2;
    const int qr = (lane >> 2);            // quad row 0..7
    uint32_t afr[2][4][4];
    #pragma unroll
    for (int tt = 0; tt < 2; ++tt) {
        const int rbase = rh * 32 + tt * 16 + qr;
        #pragma unroll
        for (int ks = 0; ks < 4; ++ks) {
            int col = ks * 16 + ac;
            afr[tt][ks][0] = pack_bf2(Qs[rbase * 68 + col],           Qs[rbase * 68 + col + 1]);
            afr[tt][ks][1] = pack_bf2(Qs[(rbase + 8) * 68 + col],     Qs[(rbase + 8) * 68 + col + 1]);
            afr[tt][ks][2] = pack_bf2(Qs[rbase * 68 + col + 8],       Qs[rbase * 68 + col + 9]);
            afr[tt][ks][3] = pack_bf2(Qs[(rbase + 8) * 68 + col + 8], Qs[(rbase + 8) * 68 + col + 9]);
        }
    }

    // prologue chunk 0
    #pragma unroll
    for (int g = 0; g < 4; ++g) {
        int seg = g * 256 + t;
        int key = seg >> 3, o = seg & 7;
        cp_async16(ksBase + (uint32_t)(key * 144 + o * 16),
                   gkb + (size_t)key * D_ + o * 8);
    }
    cp_commit();
    __syncthreads();                       // tau + cnt visible

    // per-thread candidate row pointers (4 rows)
    int* candP[4];
    float tauP[4];
    #pragma unroll
    for (int tt = 0; tt < 2; ++tt) {
        int r0 = rh * 32 + tt * 16 + qr;
        candP[tt * 2]     = g_cand + (size_t)(rowBase + r0) * CAPG;
        candP[tt * 2 + 1] = g_cand + (size_t)(rowBase + r0 + 8) * CAPG;
        tauP[tt * 2]      = tauA[r0];
        tauP[tt * 2 + 1]  = tauA[r0 + 8];
    }
    int* cntP[4];
    #pragma unroll
    for (int tt = 0; tt < 2; ++tt) {
        int r0 = rh * 32 + tt * 16 + qr;
        cntP[tt * 2]     = &cnt[r0];
        cntP[tt * 2 + 1] = &cnt[r0 + 8];
    }

    for (int chunk = 0; chunk < NCHUNK; ++chunk) {
        if (chunk + 1 < NCHUNK) {
            const int keyNext = (chunk + 1) * CK;
            const uint32_t dstB = ksBase + ((chunk + 1) & 1) * 18432;
            #pragma unroll
            for (int g = 0; g < 4; ++g) {
                int seg = g * 256 + t;
                int key = seg >> 3, o = seg & 7;
                cp_async16(dstB + (uint32_t)(key * 144 + o * 16),
                           gkb + (size_t)(keyNext + key) * D_ + o * 8);
            }
            cp_commit();
            cp_wait<1>();
        } else {
            cp_wait<0>();
        }
        __syncthreads();

        const unsigned short* Kb = Kbf + (chunk & 1) * (CK * KST);
        #pragma unroll
        for (int nt = 0; nt < 4; ++nt) {
            const int keyInChunk = ns * 32 + nt * 8 + qr;
            // B fragments once per nt, shared by both row tiles
            uint32_t bf[4][2];
            #pragma unroll
            for (int ks = 0; ks < 4; ++ks) {
                int col = ks * 16 + ac;
                bf[ks][0] = *(const uint32_t*)&Kb[keyInChunk * KST + col];
                bf[ks][1] = *(const uint32_t*)&Kb[keyInChunk * KST + col + 8];
            }
            const int kcol = chunk * CK + ns * 32 + nt * 8 + ac;
            #pragma unroll
            for (int tt = 0; tt < 2; ++tt) {
                float c0 = 0.f, c1 = 0.f, c2 = 0.f, c3 = 0.f;
                #pragma unroll
                for (int ks = 0; ks < 4; ++ks)
                    mma_bf16(c0, c1, c2, c3,
                             afr[tt][ks][0], afr[tt][ks][1],
                             afr[tt][ks][2], afr[tt][ks][3],
                             bf[ks][0], bf[ks][1]);
                c0 *= 0.125f; c1 *= 0.125f; c2 *= 0.125f; c3 *= 0.125f;
                const float ta = tauP[tt * 2], tb = tauP[tt * 2 + 1];
                if (c0 >= ta) { int p = atomicAdd(cntP[tt * 2], 1);     if (p < CAP) candP[tt * 2][p] = kcol; }
                if (c1 >= ta) { int p = atomicAdd(cntP[tt * 2], 1);     if (p < CAP) candP[tt * 2][p] = kcol + 1; }
                if (c2 >= tb) { int p = atomicAdd(cntP[tt * 2 + 1], 1); if (p < CAP) candP[tt * 2 + 1][p] = kcol; }
                if (c3 >= tb) { int p = atomicAdd(cntP[tt * 2 + 1], 1); if (p < CAP) candP[tt * 2 + 1][p] = kcol + 1; }
            }
        }
        __syncthreads();
    }

    if (t < TQ) g_cnt[rowBase + t] = cnt[t];
}

// ---------------------------------------------------------------------------
// Kernel B: one warp per query row — fp32 rescore, u64-key exact top-32, output
// ---------------------------------------------------------------------------
__global__ __launch_bounds__(256) void select_rows(
    const float* __restrict__ q, const float* __restrict__ k,
    const float* __restrict__ v, float* __restrict__ out)
{
    __shared__ unsigned long long keys[8][CAP];
    __shared__ float qs[8][64];
    __shared__ float selv[8][TOPK_];
    __shared__ int   seli[8][TOPK_];

    const int t    = threadIdx.x;
    const int lane = t & 31;
    const int w    = t >> 5;
    const unsigned full = 0xffffffffu;
    const unsigned ltmask = (1u << lane) - 1u;

    const int r = blockIdx.x * 8 + w;
    const int b = r >> 11;
    const float* kb = k + (size_t)b * L_ * D_;
    const float* vb = v + (size_t)b * L_ * D_;

    qs[w][lane]      = q[(size_t)r * D_ + lane];
    qs[w][lane + 32] = q[(size_t)r * D_ + lane + 32];
    __syncwarp();

    int n = g_cnt[r];
    const bool fb = (n < MINC || n > CAP);

    if (fb) {
        // rare fallback: fp32 bisection threshold + ballot compaction
        float nrm = qs[w][lane] * qs[w][lane] + qs[w][lane + 32] * qs[w][lane + 32];
        #pragma unroll
        for (int o = 16; o >= 1; o >>= 1) nrm += __shfl_xor_sync(full, nrm, o);
        unsigned lo = 0u, hi = 0xFFFFFFFFu;
        unsigned mid = f2sortable(Z_TAU * sqrtf(nrm) * 0.125f), tu = 0u;
        bool have = false;
        for (int it = 0; it < 34; ++it) {
            int c = 0;
            for (int j = 0; j < 64; ++j) {
                const float4* k4 = (const float4*)(kb + (size_t)(j * 32 + lane) * D_);
                float s = 0.0f;
                #pragma unroll
                for (int dg = 0; dg < 16; ++dg) {
                    float4 kv = k4[dg];
                    const float* qq = &qs[w][dg * 4];
                    s = fmaf(qq[0], kv.x, s); s = fmaf(qq[1], kv.y, s);
                    s = fmaf(qq[2], kv.z, s); s = fmaf(qq[3], kv.w, s);
                }
                c += (f2sortable(s * 0.125f) >= mid);
            }
            #pragma unroll
            for (int o = 16; o >= 1; o >>= 1) c += __shfl_xor_sync(full, c, o);
            if (c >= MINC && c <= CAP) { tu = mid; have = true; break; }
            if (c < MINC) hi = mid; else { lo = mid; tu = mid; have = true; }
            mid = lo + ((hi - lo) >> 1);
            if (mid == lo) { if (!have) tu = lo; break; }
        }
        int base = 0;
        for (int j = 0; j < 64; ++j) {
            int key = j * 32 + lane;
            const float4* k4 = (const float4*)(kb + (size_t)key * D_);
            float s = 0.0f;
            #pragma unroll
            for (int dg = 0; dg < 16; ++dg) {
                float4 kv = k4[dg];
                const float* qq = &qs[w][dg * 4];
                s = fmaf(qq[0], kv.x, s); s = fmaf(qq[1], kv.y, s);
                s = fmaf(qq[2], kv.z, s); s = fmaf(qq[3], kv.w, s);
            }
            bool cnd = f2sortable(s * 0.125f) >= tu;
            unsigned m = __ballot_sync(full, cnd);
            if (cnd) {
                int pos = base + __popc(m & ltmask);
                if (pos < CAP) keys[w][pos] = (unsigned long long)key;  // stage idx
            }
            base += __popc(m);
        }
        n = base < CAP ? base : CAP;
        __syncwarp();
    }

    // gather my candidates (i = lane + 32j slots; same-lane read/write of keys)
    int   midx[5];
    float mval[5];
    unsigned long long mkey[5] = {0ull, 0ull, 0ull, 0ull, 0ull}; // 0 = sentinel
    int mc = 0;
    const int* candRow = g_cand + (size_t)r * CAPG;
    for (int i = lane; i < n; i += 32) {
        int idx = fb ? (int)keys[w][i] : candRow[i];
        const float4* k4 = (const float4*)(kb + (size_t)idx * D_);
        float s = 0.0f;
        #pragma unroll
        for (int dg = 0; dg < 16; ++dg) {
            float4 kv = k4[dg];
            const float* qq = &qs[w][dg * 4];
            s = fmaf(qq[0], kv.x, s); s = fmaf(qq[1], kv.y, s);
            s = fmaf(qq[2], kv.z, s); s = fmaf(qq[3], kv.w, s);
        }
        s *= 0.125f;
        unsigned long long key =
            ((unsigned long long)f2sortable(s) << 32) | (unsigned)(2047 - idx);
        keys[w][i] = key;
        midx[mc] = idx; mval[mc] = s; mkey[mc] = key; ++mc;
    }
    __syncwarp();

    // exact top-32 by rank (u64 compares: val desc, tie -> lower idx)
    int rk[5] = {0, 0, 0, 0, 0};
    for (int j = 0; j < n; ++j) {
        unsigned long long kj = keys[w][j];
        #pragma unroll
        for (int c = 0; c < 5; ++c) rk[c] += (kj > mkey[c]);
    }
    #pragma unroll
    for (int c = 0; c < 5; ++c)
        if (c < mc && rk[c] < TOPK_) { selv[w][rk[c]] = mval[c]; seli[w][rk[c]] = midx[c]; }
    __syncwarp();

    // output
    float a0 = 0.0f, a1 = 0.0f;
    #pragma unroll
    for (int j = 0; j < TOPK_; ++j) {
        float vv = selv[w][j];
        const float* vrow = vb + (size_t)seli[w][j] * D_;
        a0 = fmaf(vv, vrow[lane], a0);
        a1 = fmaf(vv, vrow[lane + 32], a1);
    }
    out[(size_t)r * D_ + lane]      = a0;
    out[(size_t)r * D_ + lane + 32] = a1;
}

// ---------------------------------------------------------------------------
extern "C" void kernel_launch(void* const* d_in, const int* in_sizes, int n_in,
                              void* d_out, int out_size)
{
    const float* q = (const float*)d_in[0];
    const float* k = (const float*)d_in[1];
    const float* v = (const float*)d_in[2];
    float* out = (float*)d_out;

    convert_k<<<(B_ * L_ * D_ / 4) / 256, 256>>>(k);

    cudaFuncSetAttribute(score_harvest,
                         cudaFuncAttributeMaxDynamicSharedMemorySize, SMEM_A);
    score_harvest<<<NBLK, 256, SMEM_A>>>(q);

    select_rows<<<B_ * L_ / 8, 256>>>(q, k, v, out);
}

// round 11
// speedup vs baseline: 1.3569x; 1.3569x over previous
#include <cuda_runtime.h>
#include <cuda_bf16.h>
#include <cstdint>

// Problem constants
#define B_    8
#define L_    2048
#define D_    64
#define TOPK_ 32

// Kernel A tiling (R9-proven TQ=32 config)
#define TQ     32
#define CK     128
#define NCHUNK (L_ / CK)         // 16
#define NBLK   (B_ * L_ / TQ)    // 512
#define BPB    (L_ / TQ)         // 64

// Selection: analytic threshold tau = Z_TAU * ||q|| / 8
// count ~ Binomial(2048, P(Z>1.70)=.0446): E=91.3, sd=9.3
#define Z_TAU 1.70f
#define MINC  40                 // containment guard (P<2e-8/row)
#define CAP   144                // overflow guard  (P<1e-8/row)
#define CAPG  160                // global candidate stride
#define TRIM  48                 // rescore only approx-rank < 48

#define KST  72                  // Kbf smem row stride (bf16 elems)

// ---- kernel A dynamic smem layout (bytes) ----
#define OFF_KBF   0              // bf16 [2][128][72] = 36864
#define OFF_QS    36864          // f32  [32][68]     =  8704
#define OFF_TAU   45568          // f32  [32]
#define OFF_CNT   45696          // int  [32]
#define SMEM_A    45824

// Global scratch
__device__ __nv_bfloat16 gKbf[(size_t)B_ * L_ * D_];      // 2 MB
__device__ int g_cnt[B_ * L_];
__device__ unsigned g_cand[(size_t)B_ * L_ * CAPG];       // packed (s16<<16)|idx

__device__ __forceinline__ unsigned f2sortable(float f) {
    unsigned bb = __float_as_uint(f);
    return (bb & 0x80000000u) ? ~bb : (bb | 0x80000000u);
}
__device__ __forceinline__ float s2f(unsigned u) {        // inverse of f2sortable
    unsigned bb = (u & 0x80000000u) ? (u & 0x7FFFFFFFu) : ~u;
    return __uint_as_float(bb);
}
__device__ __forceinline__ unsigned short f2s16(float f) { // sortable bf16
    unsigned short b = __bfloat16_as_ushort(__float2bfloat16(f));
    return (b & 0x8000) ? (unsigned short)~b : (unsigned short)(b | 0x8000);
}

__device__ __forceinline__ uint32_t pack_bf2(float lo, float hi) {
    __nv_bfloat162 h2 = __floats2bfloat162_rn(lo, hi);
    return *reinterpret_cast<uint32_t*>(&h2);
}

__device__ __forceinline__ void mma_bf16(
    float& c0, float& c1, float& c2, float& c3,
    uint32_t a0, uint32_t a1, uint32_t a2, uint32_t a3,
    uint32_t b0, uint32_t b1)
{
    asm volatile(
        "mma.sync.aligned.m16n8k16.row.col.f32.bf16.bf16.f32 "
        "{%0,%1,%2,%3}, {%4,%5,%6,%7}, {%8,%9}, {%0,%1,%2,%3};\n"
        : "+f"(c0), "+f"(c1), "+f"(c2), "+f"(c3)
        : "r"(a0), "r"(a1), "r"(a2), "r"(a3), "r"(b0), "r"(b1));
}

__device__ __forceinline__ void cp_async16(uint32_t smem_dst, const void* gsrc) {
    asm volatile("cp.async.cg.shared.global [%0], [%1], 16;\n"
                 :: "r"(smem_dst), "l"(gsrc));
}
__device__ __forceinline__ void cp_commit() {
    asm volatile("cp.async.commit_group;\n");
}
template <int N>
__device__ __forceinline__ void cp_wait() {
    asm volatile("cp.async.wait_group %0;\n" :: "n"(N));
}

// ---------------------------------------------------------------------------
// Kernel 0: K fp32 -> bf16
// ---------------------------------------------------------------------------
__global__ __launch_bounds__(256) void convert_k(const float* __restrict__ k) {
    int idx = blockIdx.x * 256 + threadIdx.x;
    float4 kv = *(const float4*)(k + (size_t)idx * 4);
    uint2 o;
    o.x = pack_bf2(kv.x, kv.y);
    o.y = pack_bf2(kv.z, kv.w);
    *(uint2*)((unsigned short*)gKbf + (size_t)idx * 4) = o;
}

// ---------------------------------------------------------------------------
// Kernel A: HMMA scores + analytic-threshold harvest of packed (score,idx)
// ---------------------------------------------------------------------------
__global__ __launch_bounds__(256, 3) void score_harvest(
    const float* __restrict__ q)
{
    extern __shared__ __align__(16) char smem[];
    unsigned short* Kbf = (unsigned short*)(smem + OFF_KBF);
    float* Qs   = (float*)(smem + OFF_QS);
    float* tauA = (float*)(smem + OFF_TAU);
    int*   cnt  = (int*)(smem + OFF_CNT);

    const int t    = threadIdx.x;
    const int lane = t & 31;
    const int w    = t >> 5;
    const unsigned full = 0xffffffffu;

    const int rowBase = blockIdx.x * TQ;
    const int b       = blockIdx.x / BPB;
    const __nv_bfloat16* gkb = gKbf + (size_t)b * L_ * D_;
    const uint32_t ksBase = (uint32_t)__cvta_generic_to_shared(Kbf);

    for (int i = t; i < TQ * 16; i += 256) {
        int row = i >> 4, dg4 = (i & 15) << 2;
        *(float4*)(Qs + row * 68 + dg4) =
            *(const float4*)(q + ((size_t)(rowBase + row)) * D_ + dg4);
    }
    if (t < TQ) cnt[t] = 0;
    __syncthreads();

    // per-row analytic tau (warp w -> rows 4w..4w+3)
    for (int rr = 0; rr < 4; ++rr) {
        int row = w * 4 + rr;
        float x = Qs[row * 68 + lane], y = Qs[row * 68 + lane + 32];
        float nrm = x * x + y * y;
        #pragma unroll
        for (int o = 16; o >= 1; o >>= 1) nrm += __shfl_xor_sync(full, nrm, o);
        if (lane == 0) tauA[row] = Z_TAU * sqrtf(nrm) * 0.125f;
    }

    // A fragments (Q) once
    const int rg = w >> 2;
    const int ns = w & 3;
    const int ar = rg * 16 + (lane >> 2);
    const int ac = (lane & 3) * 2;
    uint32_t afr[4][4];
    #pragma unroll
    for (int ks = 0; ks < 4; ++ks) {
        int col = ks * 16 + ac;
        afr[ks][0] = pack_bf2(Qs[ar * 68 + col],           Qs[ar * 68 + col + 1]);
        afr[ks][1] = pack_bf2(Qs[(ar + 8) * 68 + col],     Qs[(ar + 8) * 68 + col + 1]);
        afr[ks][2] = pack_bf2(Qs[ar * 68 + col + 8],       Qs[ar * 68 + col + 9]);
        afr[ks][3] = pack_bf2(Qs[(ar + 8) * 68 + col + 8], Qs[(ar + 8) * 68 + col + 9]);
    }

    // prologue chunk 0
    #pragma unroll
    for (int g = 0; g < 4; ++g) {
        int seg = g * 256 + t;
        int key = seg >> 3, o = seg & 7;
        cp_async16(ksBase + (uint32_t)(key * 144 + o * 16),
                   gkb + (size_t)key * D_ + o * 8);
    }
    cp_commit();
    __syncthreads();                       // tau + cnt visible

    unsigned* candRowA = g_cand + (size_t)(rowBase + ar) * CAPG;
    unsigned* candRowB = g_cand + (size_t)(rowBase + ar + 8) * CAPG;

    for (int chunk = 0; chunk < NCHUNK; ++chunk) {
        if (chunk + 1 < NCHUNK) {
            const int keyNext = (chunk + 1) * CK;
            const uint32_t dstB = ksBase + ((chunk + 1) & 1) * 18432;
            #pragma unroll
            for (int g = 0; g < 4; ++g) {
                int seg = g * 256 + t;
                int key = seg >> 3, o = seg & 7;
                cp_async16(dstB + (uint32_t)(key * 144 + o * 16),
                           gkb + (size_t)(keyNext + key) * D_ + o * 8);
            }
            cp_commit();
            cp_wait<1>();
        } else {
            cp_wait<0>();
        }
        __syncthreads();

        const unsigned short* Kb = Kbf + (chunk & 1) * (CK * KST);
        const float tau_a = tauA[ar], tau_b = tauA[ar + 8];
        #pragma unroll
        for (int nt = 0; nt < 4; ++nt) {
            const int keyInChunk = ns * 32 + nt * 8 + (lane >> 2);
            float c0 = 0.f, c1 = 0.f, c2 = 0.f, c3 = 0.f;
            #pragma unroll
            for (int ks = 0; ks < 4; ++ks) {
                int col = ks * 16 + ac;
                uint32_t b0 = *(const uint32_t*)&Kb[keyInChunk * KST + col];
                uint32_t b1 = *(const uint32_t*)&Kb[keyInChunk * KST + col + 8];
                mma_bf16(c0, c1, c2, c3,
                         afr[ks][0], afr[ks][1], afr[ks][2], afr[ks][3], b0, b1);
            }
            const unsigned kcol = chunk * CK + ns * 32 + nt * 8 + ac;
            c0 *= 0.125f; c1 *= 0.125f; c2 *= 0.125f; c3 *= 0.125f;
            if (c0 >= tau_a) { int p = atomicAdd(&cnt[ar], 1);     if (p < CAP) candRowA[p] = ((unsigned)f2s16(c0) << 16) | kcol; }
            if (c1 >= tau_a) { int p = atomicAdd(&cnt[ar], 1);     if (p < CAP) candRowA[p] = ((unsigned)f2s16(c1) << 16) | (kcol + 1); }
            if (c2 >= tau_b) { int p = atomicAdd(&cnt[ar + 8], 1); if (p < CAP) candRowB[p] = ((unsigned)f2s16(c2) << 16) | kcol; }
            if (c3 >= tau_b) { int p = atomicAdd(&cnt[ar + 8], 1); if (p < CAP) candRowB[p] = ((unsigned)f2s16(c3) << 16) | (kcol + 1); }
        }
        __syncthreads();
    }

    if (t < TQ) g_cnt[rowBase + t] = cnt[t];
}

// ---------------------------------------------------------------------------
// Kernel B: one warp per row — approx trim to 48, sector-perfect cooperative
// fp32 rescore, u64-key exact top-32, output
// ---------------------------------------------------------------------------
__global__ __launch_bounds__(256) void select_rows(
    const float* __restrict__ q, const float* __restrict__ k,
    const float* __restrict__ v, float* __restrict__ out)
{
    __shared__ float qs[8][64];
    __shared__ unsigned pk[8][CAP];
    __shared__ unsigned short ids[8][CAP];
    __shared__ unsigned long long skey[8][CAP];
    __shared__ int   seli[8][TOPK_];
    __shared__ float selv[8][TOPK_];

    const int t    = threadIdx.x;
    const int lane = t & 31;
    const int w    = t >> 5;
    const unsigned full = 0xffffffffu;
    const unsigned ltmask = (1u << lane) - 1u;

    const int r = blockIdx.x * 8 + w;
    const int b = r >> 11;
    const float* kb = k + (size_t)b * L_ * D_;
    const float* vb = v + (size_t)b * L_ * D_;

    qs[w][lane]      = q[(size_t)r * D_ + lane];
    qs[w][lane + 32] = q[(size_t)r * D_ + lane + 32];
    __syncwarp();

    int n = g_cnt[r];
    const bool fb = (n < MINC || n > CAP);
    int m;

    if (!fb) {
        // ---- approx trim: keep packed-rank < TRIM ----
        const unsigned* candRow = g_cand + (size_t)r * CAPG;
        unsigned mp[5];
        int mc = 0;
        for (int i = lane; i < n; i += 32) { unsigned p = candRow[i]; pk[w][i] = p; mp[mc++] = p; }
        __syncwarp();
        int rk[5] = {0, 0, 0, 0, 0};
        for (int j = 0; j < n; ++j) {
            unsigned pj = pk[w][j];
            #pragma unroll
            for (int c = 0; c < 5; ++c) rk[c] += (pj > mp[c]);
        }
        int base = 0;
        #pragma unroll
        for (int c = 0; c < 5; ++c) {
            bool sv = (c < mc) && (rk[c] < TRIM);
            unsigned msk = __ballot_sync(full, sv);
            if (sv) {
                int pos = base + __popc(msk & ltmask);
                ids[w][pos] = (unsigned short)(mp[c] & 0xFFFFu);
            }
            base += __popc(msk);
        }
        m = base;                                   // = min(n, TRIM)
        __syncwarp();
    } else {
        // ---- rare fallback: fp32 bisection + ballot compaction ----
        float nrm = qs[w][lane] * qs[w][lane] + qs[w][lane + 32] * qs[w][lane + 32];
        #pragma unroll
        for (int o = 16; o >= 1; o >>= 1) nrm += __shfl_xor_sync(full, nrm, o);
        unsigned lo = 0u, hi = 0xFFFFFFFFu;
        unsigned mid = f2sortable(Z_TAU * sqrtf(nrm) * 0.125f), tu = 0u;
        bool have = false;
        for (int it = 0; it < 34; ++it) {
            int c = 0;
            for (int j = 0; j < 64; ++j) {
                const float4* k4 = (const float4*)(kb + (size_t)(j * 32 + lane) * D_);
                float s = 0.0f;
                #pragma unroll
                for (int dg = 0; dg < 16; ++dg) {
                    float4 kv = k4[dg];
                    const float* qq = &qs[w][dg * 4];
                    s = fmaf(qq[0], kv.x, s); s = fmaf(qq[1], kv.y, s);
                    s = fmaf(qq[2], kv.z, s); s = fmaf(qq[3], kv.w, s);
                }
                c += (f2sortable(s * 0.125f) >= mid);
            }
            #pragma unroll
            for (int o = 16; o >= 1; o >>= 1) c += __shfl_xor_sync(full, c, o);
            if (c >= MINC && c <= CAP) { tu = mid; have = true; break; }
            if (c < MINC) hi = mid; else { lo = mid; tu = mid; have = true; }
            mid = lo + ((hi - lo) >> 1);
            if (mid == lo) { if (!have) tu = lo; break; }
        }
        int base = 0;
        for (int j = 0; j < 64; ++j) {
            int key = j * 32 + lane;
            const float4* k4 = (const float4*)(kb + (size_t)key * D_);
            float s = 0.0f;
            #pragma unroll
            for (int dg = 0; dg < 16; ++dg) {
                float4 kv = k4[dg];
                const float* qq = &qs[w][dg * 4];
                s = fmaf(qq[0], kv.x, s); s = fmaf(qq[1], kv.y, s);
                s = fmaf(qq[2], kv.z, s); s = fmaf(qq[3], kv.w, s);
            }
            bool cnd = f2sortable(s * 0.125f) >= tu;
            unsigned mk = __ballot_sync(full, cnd);
            if (cnd) {
                int pos = base + __popc(mk & ltmask);
                if (pos < CAP) ids[w][pos] = (unsigned short)key;
            }
            base += __popc(mk);
        }
        m = base < CAP ? base : CAP;
        __syncwarp();
    }

    // ---- cooperative rescore: 4-lane groups, 8 candidates/iter, full sectors ----
    const int g4 = lane >> 2, l4 = lane & 3;
    float4 qf[4];
    #pragma unroll
    for (int j = 0; j < 4; ++j) qf[j] = *(const float4*)&qs[w][l4 * 4 + j * 16];

    for (int i = 0; i < m; i += 8) {
        int slot = i + g4;
        float s = 0.0f;
        int idx = 0;
        if (slot < m) {
            idx = ids[w][slot];
            const float4* kr = (const float4*)(kb + (size_t)idx * D_);
            #pragma unroll
            for (int j = 0; j < 4; ++j) {
                float4 kv = kr[l4 + j * 4];
                s = fmaf(qf[j].x, kv.x, s); s = fmaf(qf[j].y, kv.y, s);
                s = fmaf(qf[j].z, kv.z, s); s = fmaf(qf[j].w, kv.w, s);
            }
        }
        s += __shfl_xor_sync(full, s, 1);
        s += __shfl_xor_sync(full, s, 2);
        if (slot < m && l4 == 0) {
            s *= 0.125f;
            skey[w][slot] = ((unsigned long long)f2sortable(s) << 32)
                          | (unsigned)(2047 - idx);
        }
    }
    __syncwarp();

    // ---- exact top-32 among m (u64: val desc, tie -> lower idx) ----
    unsigned long long fk[5] = {0ull, 0ull, 0ull, 0ull, 0ull};
    int mc2 = 0;
    for (int i = lane; i < m; i += 32) { fk[mc2] = skey[w][i]; ++mc2; }
    int rk2[5] = {0, 0, 0, 0, 0};
    for (int j = 0; j < m; ++j) {
        unsigned long long kj = skey[w][j];
        #pragma unroll
        for (int c = 0; c < 5; ++c) rk2[c] += (kj > fk[c]);
    }
    #pragma unroll
    for (int c = 0; c < 5; ++c) {
        if (c < mc2 && rk2[c] < TOPK_) {
            seli[w][rk2[c]] = 2047 - (int)(fk[c] & 0xFFFFFFFFull);
            selv[w][rk2[c]] = s2f((unsigned)(fk[c] >> 32));
        }
    }
    __syncwarp();

    // ---- output ----
    float a0 = 0.0f, a1 = 0.0f;
    #pragma unroll
    for (int j = 0; j < TOPK_; ++j) {
        float vv = selv[w][j];
        const float* vrow = vb + (size_t)seli[w][j] * D_;
        a0 = fmaf(vv, vrow[lane], a0);
        a1 = fmaf(vv, vrow[lane + 32], a1);
    }
    out[(size_t)r * D_ + lane]      = a0;
    out[(size_t)r * D_ + lane + 32] = a1;
}

// ---------------------------------------------------------------------------
extern "C" void kernel_launch(void* const* d_in, const int* in_sizes, int n_in,
                              void* d_out, int out_size)
{
    const float* q = (const float*)d_in[0];
    const float* k = (const float*)d_in[1];
    const float* v = (const float*)d_in[2];
    float* out = (float*)d_out;

    convert_k<<<(B_ * L_ * D_ / 4) / 256, 256>>>(k);

    cudaFuncSetAttribute(score_harvest,
                         cudaFuncAttributeMaxDynamicSharedMemorySize, SMEM_A);
    score_harvest<<<NBLK, 256, SMEM_A>>>(q);

    select_rows<<<B_ * L_ / 8, 256>>>(q, k, v, out);
}

// round 12
// speedup vs baseline: 1.4179x; 1.0449x over previous
#include <cuda_runtime.h>
#include <cuda_bf16.h>
#include <cstdint>

// Problem constants
#define B_    8
#define L_    2048
#define D_    64
#define TOPK_ 32

// Kernel A tiling
#define TQ     32
#define CK     128
#define NCHUNK (L_ / CK)         // 16
#define NBLK   (B_ * L_ / TQ)    // 512
#define BPB    (L_ / TQ)         // 64

// Selection: analytic threshold tau = Z_TAU * ||q|| / 8
// count ~ Binomial(2048, P(Z>1.70)=.0446): E=91.3, sd=9.3
#define Z_TAU 1.70f
#define MINC  40                 // containment guard (P<2e-8/row)
#define CAP   144                // overflow guard  (P<1e-8/row)
#define CAPG  160                // global candidate stride
#define TRIM  40                 // rescore only approx-rank < 40 (8-rank margin)

#define KST  72                  // Kbf smem row stride (bf16 elems)

// ---- kernel A dynamic smem layout (bytes) ----
#define OFF_KBF   0              // bf16 [2][128][72] = 36864
#define OFF_QS    36864          // f32  [32][68]     =  8704
#define OFF_TAU   45568          // f32  [32]
#define OFF_CNT   45696          // int  [32]
#define SMEM_A    45824          // x4 blocks/SM = 183296 <= 228KB

// Global scratch
__device__ __nv_bfloat16 gKbf[(size_t)B_ * L_ * D_];      // 2 MB
__device__ int g_cnt[B_ * L_];
__device__ unsigned g_cand[(size_t)B_ * L_ * CAPG];       // packed (s16<<16)|idx

__device__ __forceinline__ unsigned f2sortable(float f) {
    unsigned bb = __float_as_uint(f);
    return (bb & 0x80000000u) ? ~bb : (bb | 0x80000000u);
}
__device__ __forceinline__ float s2f(unsigned u) {        // inverse of f2sortable
    unsigned bb = (u & 0x80000000u) ? (u & 0x7FFFFFFFu) : ~u;
    return __uint_as_float(bb);
}
__device__ __forceinline__ unsigned short f2s16(float f) { // sortable bf16
    unsigned short b = __bfloat16_as_ushort(__float2bfloat16(f));
    return (b & 0x8000) ? (unsigned short)~b : (unsigned short)(b | 0x8000);
}

__device__ __forceinline__ uint32_t pack_bf2(float lo, float hi) {
    __nv_bfloat162 h2 = __floats2bfloat162_rn(lo, hi);
    return *reinterpret_cast<uint32_t*>(&h2);
}

__device__ __forceinline__ void mma_bf16(
    float& c0, float& c1, float& c2, float& c3,
    uint32_t a0, uint32_t a1, uint32_t a2, uint32_t a3,
    uint32_t b0, uint32_t b1)
{
    asm volatile(
        "mma.sync.aligned.m16n8k16.row.col.f32.bf16.bf16.f32 "
        "{%0,%1,%2,%3}, {%4,%5,%6,%7}, {%8,%9}, {%0,%1,%2,%3};\n"
        : "+f"(c0), "+f"(c1), "+f"(c2), "+f"(c3)
        : "r"(a0), "r"(a1), "r"(a2), "r"(a3), "r"(b0), "r"(b1));
}

__device__ __forceinline__ void cp_async16(uint32_t smem_dst, const void* gsrc) {
    asm volatile("cp.async.cg.shared.global [%0], [%1], 16;\n"
                 :: "r"(smem_dst), "l"(gsrc));
}
__device__ __forceinline__ void cp_commit() {
    asm volatile("cp.async.commit_group;\n");
}
template <int N>
__device__ __forceinline__ void cp_wait() {
    asm volatile("cp.async.wait_group %0;\n" :: "n"(N));
}

// ---------------------------------------------------------------------------
// Kernel 0: K fp32 -> bf16
// ---------------------------------------------------------------------------
__global__ __launch_bounds__(256) void convert_k(const float* __restrict__ k) {
    int idx = blockIdx.x * 256 + threadIdx.x;
    float4 kv = *(const float4*)(k + (size_t)idx * 4);
    uint2 o;
    o.x = pack_bf2(kv.x, kv.y);
    o.y = pack_bf2(kv.z, kv.w);
    *(uint2*)((unsigned short*)gKbf + (size_t)idx * 4) = o;
}

// ---------------------------------------------------------------------------
// Kernel A: HMMA scores + analytic-threshold harvest of packed (score,idx)
// occ 4 -> 592 slots >= 512 blocks: single wave
// ---------------------------------------------------------------------------
__global__ __launch_bounds__(256, 4) void score_harvest(
    const float* __restrict__ q)
{
    extern __shared__ __align__(16) char smem[];
    unsigned short* Kbf = (unsigned short*)(smem + OFF_KBF);
    float* Qs   = (float*)(smem + OFF_QS);
    float* tauA = (float*)(smem + OFF_TAU);
    int*   cnt  = (int*)(smem + OFF_CNT);

    const int t    = threadIdx.x;
    const int lane = t & 31;
    const int w    = t >> 5;
    const unsigned full = 0xffffffffu;

    const int rowBase = blockIdx.x * TQ;
    const int b       = blockIdx.x / BPB;
    const __nv_bfloat16* gkb = gKbf + (size_t)b * L_ * D_;
    const uint32_t ksBase = (uint32_t)__cvta_generic_to_shared(Kbf);

    for (int i = t; i < TQ * 16; i += 256) {
        int row = i >> 4, dg4 = (i & 15) << 2;
        *(float4*)(Qs + row * 68 + dg4) =
            *(const float4*)(q + ((size_t)(rowBase + row)) * D_ + dg4);
    }
    if (t < TQ) cnt[t] = 0;
    __syncthreads();

    // per-row analytic tau (warp w -> rows 4w..4w+3)
    for (int rr = 0; rr < 4; ++rr) {
        int row = w * 4 + rr;
        float x = Qs[row * 68 + lane], y = Qs[row * 68 + lane + 32];
        float nrm = x * x + y * y;
        #pragma unroll
        for (int o = 16; o >= 1; o >>= 1) nrm += __shfl_xor_sync(full, nrm, o);
        if (lane == 0) tauA[row] = Z_TAU * sqrtf(nrm) * 0.125f;
    }

    // A fragments (Q) once
    const int rg = w >> 2;
    const int ns = w & 3;
    const int ar = rg * 16 + (lane >> 2);
    const int ac = (lane & 3) * 2;
    uint32_t afr[4][4];
    #pragma unroll
    for (int ks = 0; ks < 4; ++ks) {
        int col = ks * 16 + ac;
        afr[ks][0] = pack_bf2(Qs[ar * 68 + col],           Qs[ar * 68 + col + 1]);
        afr[ks][1] = pack_bf2(Qs[(ar + 8) * 68 + col],     Qs[(ar + 8) * 68 + col + 1]);
        afr[ks][2] = pack_bf2(Qs[ar * 68 + col + 8],       Qs[ar * 68 + col + 9]);
        afr[ks][3] = pack_bf2(Qs[(ar + 8) * 68 + col + 8], Qs[(ar + 8) * 68 + col + 9]);
    }

    // prologue chunk 0
    #pragma unroll
    for (int g = 0; g < 4; ++g) {
        int seg = g * 256 + t;
        int key = seg >> 3, o = seg & 7;
        cp_async16(ksBase + (uint32_t)(key * 144 + o * 16),
                   gkb + (size_t)key * D_ + o * 8);
    }
    cp_commit();
    __syncthreads();                       // tau + cnt visible

    unsigned* candRowA = g_cand + (size_t)(rowBase + ar) * CAPG;
    unsigned* candRowB = g_cand + (size_t)(rowBase + ar + 8) * CAPG;

    for (int chunk = 0; chunk < NCHUNK; ++chunk) {
        if (chunk + 1 < NCHUNK) {
            const int keyNext = (chunk + 1) * CK;
            const uint32_t dstB = ksBase + ((chunk + 1) & 1) * 18432;
            #pragma unroll
            for (int g = 0; g < 4; ++g) {
                int seg = g * 256 + t;
                int key = seg >> 3, o = seg & 7;
                cp_async16(dstB + (uint32_t)(key * 144 + o * 16),
                           gkb + (size_t)(keyNext + key) * D_ + o * 8);
            }
            cp_commit();
            cp_wait<1>();
        } else {
            cp_wait<0>();
        }
        __syncthreads();

        const unsigned short* Kb = Kbf + (chunk & 1) * (CK * KST);
        const float tau_a = tauA[ar], tau_b = tauA[ar + 8];
        #pragma unroll
        for (int nt = 0; nt < 4; ++nt) {
            const int keyInChunk = ns * 32 + nt * 8 + (lane >> 2);
            float c0 = 0.f, c1 = 0.f, c2 = 0.f, c3 = 0.f;
            #pragma unroll
            for (int ks = 0; ks < 4; ++ks) {
                int col = ks * 16 + ac;
                uint32_t b0 = *(const uint32_t*)&Kb[keyInChunk * KST + col];
                uint32_t b1 = *(const uint32_t*)&Kb[keyInChunk * KST + col + 8];
                mma_bf16(c0, c1, c2, c3,
                         afr[ks][0], afr[ks][1], afr[ks][2], afr[ks][3], b0, b1);
            }
            const unsigned kcol = chunk * CK + ns * 32 + nt * 8 + ac;
            c0 *= 0.125f; c1 *= 0.125f; c2 *= 0.125f; c3 *= 0.125f;
            if (c0 >= tau_a) { int p = atomicAdd(&cnt[ar], 1);     if (p < CAP) candRowA[p] = ((unsigned)f2s16(c0) << 16) | kcol; }
            if (c1 >= tau_a) { int p = atomicAdd(&cnt[ar], 1);     if (p < CAP) candRowA[p] = ((unsigned)f2s16(c1) << 16) | (kcol + 1); }
            if (c2 >= tau_b) { int p = atomicAdd(&cnt[ar + 8], 1); if (p < CAP) candRowB[p] = ((unsigned)f2s16(c2) << 16) | kcol; }
            if (c3 >= tau_b) { int p = atomicAdd(&cnt[ar + 8], 1); if (p < CAP) candRowB[p] = ((unsigned)f2s16(c3) << 16) | (kcol + 1); }
        }
        __syncthreads();
    }

    if (t < TQ) g_cnt[rowBase + t] = cnt[t];
}

// ---------------------------------------------------------------------------
// Kernel B: one warp per row — approx trim to TRIM, sector-perfect cooperative
// fp32 rescore, u64-key exact top-32, output
// ---------------------------------------------------------------------------
__global__ __launch_bounds__(256) void select_rows(
    const float* __restrict__ q, const float* __restrict__ k,
    const float* __restrict__ v, float* __restrict__ out)
{
    __shared__ float qs[8][64];
    __shared__ unsigned pk[8][CAP];
    __shared__ unsigned short ids[8][CAP];
    __shared__ unsigned long long skey[8][CAP];
    __shared__ int   seli[8][TOPK_];
    __shared__ float selv[8][TOPK_];

    const int t    = threadIdx.x;
    const int lane = t & 31;
    const int w    = t >> 5;
    const unsigned full = 0xffffffffu;
    const unsigned ltmask = (1u << lane) - 1u;

    const int r = blockIdx.x * 8 + w;
    const int b = r >> 11;
    const float* kb = k + (size_t)b * L_ * D_;
    const float* vb = v + (size_t)b * L_ * D_;

    qs[w][lane]      = q[(size_t)r * D_ + lane];
    qs[w][lane + 32] = q[(size_t)r * D_ + lane + 32];
    __syncwarp();

    int n = g_cnt[r];
    const bool fb = (n < MINC || n > CAP);
    int m;

    if (!fb) {
        // ---- approx trim: keep packed-rank < TRIM ----
        const unsigned* candRow = g_cand + (size_t)r * CAPG;
        unsigned mp[5];
        int mc = 0;
        for (int i = lane; i < n; i += 32) { unsigned p = candRow[i]; pk[w][i] = p; mp[mc++] = p; }
        __syncwarp();
        int rk[5] = {0, 0, 0, 0, 0};
        for (int j = 0; j < n; ++j) {
            unsigned pj = pk[w][j];
            #pragma unroll
            for (int c = 0; c < 5; ++c) rk[c] += (pj > mp[c]);
        }
        int base = 0;
        #pragma unroll
        for (int c = 0; c < 5; ++c) {
            bool sv = (c < mc) && (rk[c] < TRIM);
            unsigned msk = __ballot_sync(full, sv);
            if (sv) {
                int pos = base + __popc(msk & ltmask);
                ids[w][pos] = (unsigned short)(mp[c] & 0xFFFFu);
            }
            base += __popc(msk);
        }
        m = base;
        __syncwarp();
    } else {
        // ---- rare fallback: fp32 bisection + ballot compaction ----
        float nrm = qs[w][lane] * qs[w][lane] + qs[w][lane + 32] * qs[w][lane + 32];
        #pragma unroll
        for (int o = 16; o >= 1; o >>= 1) nrm += __shfl_xor_sync(full, nrm, o);
        unsigned lo = 0u, hi = 0xFFFFFFFFu;
        unsigned mid = f2sortable(Z_TAU * sqrtf(nrm) * 0.125f), tu = 0u;
        bool have = false;
        for (int it = 0; it < 34; ++it) {
            int c = 0;
            for (int j = 0; j < 64; ++j) {
                const float4* k4 = (const float4*)(kb + (size_t)(j * 32 + lane) * D_);
                float s = 0.0f;
                #pragma unroll
                for (int dg = 0; dg < 16; ++dg) {
                    float4 kv = k4[dg];
                    const float* qq = &qs[w][dg * 4];
                    s = fmaf(qq[0], kv.x, s); s = fmaf(qq[1], kv.y, s);
                    s = fmaf(qq[2], kv.z, s); s = fmaf(qq[3], kv.w, s);
                }
                c += (f2sortable(s * 0.125f) >= mid);
            }
            #pragma unroll
            for (int o = 16; o >= 1; o >>= 1) c += __shfl_xor_sync(full, c, o);
            if (c >= MINC && c <= CAP) { tu = mid; have = true; break; }
            if (c < MINC) hi = mid; else { lo = mid; tu = mid; have = true; }
            mid = lo + ((hi - lo) >> 1);
            if (mid == lo) { if (!have) tu = lo; break; }
        }
        int base = 0;
        for (int j = 0; j < 64; ++j) {
            int key = j * 32 + lane;
            const float4* k4 = (const float4*)(kb + (size_t)key * D_);
            float s = 0.0f;
            #pragma unroll
            for (int dg = 0; dg < 16; ++dg) {
                float4 kv = k4[dg];
                const float* qq = &qs[w][dg * 4];
                s = fmaf(qq[0], kv.x, s); s = fmaf(qq[1], kv.y, s);
                s = fmaf(qq[2], kv.z, s); s = fmaf(qq[3], kv.w, s);
            }
            bool cnd = f2sortable(s * 0.125f) >= tu;
            unsigned mk = __ballot_sync(full, cnd);
            if (cnd) {
                int pos = base + __popc(mk & ltmask);
                if (pos < CAP) ids[w][pos] = (unsigned short)key;
            }
            base += __popc(mk);
        }
        m = base < CAP ? base : CAP;
        __syncwarp();
    }

    // ---- cooperative rescore: 4-lane groups, 8 candidates/iter, full sectors ----
    const int g4 = lane >> 2, l4 = lane & 3;
    float4 qf[4];
    #pragma unroll
    for (int j = 0; j < 4; ++j) qf[j] = *(const float4*)&qs[w][l4 * 4 + j * 16];

    for (int i = 0; i < m; i += 8) {
        int slot = i + g4;
        float s = 0.0f;
        int idx = 0;
        if (slot < m) {
            idx = ids[w][slot];
            const float4* kr = (const float4*)(kb + (size_t)idx * D_);
            #pragma unroll
            for (int j = 0; j < 4; ++j) {
                float4 kv = kr[l4 + j * 4];
                s = fmaf(qf[j].x, kv.x, s); s = fmaf(qf[j].y, kv.y, s);
                s = fmaf(qf[j].z, kv.z, s); s = fmaf(qf[j].w, kv.w, s);
            }
        }
        s += __shfl_xor_sync(full, s, 1);
        s += __shfl_xor_sync(full, s, 2);
        if (slot < m && l4 == 0) {
            s *= 0.125f;
            skey[w][slot] = ((unsigned long long)f2sortable(s) << 32)
                          | (unsigned)(2047 - idx);
        }
    }
    __syncwarp();

    // ---- exact top-32 among m (u64: val desc, tie -> lower idx) ----
    unsigned long long fk[5] = {0ull, 0ull, 0ull, 0ull, 0ull};
    int mc2 = 0;
    for (int i = lane; i < m; i += 32) { fk[mc2] = skey[w][i]; ++mc2; }
    int rk2[5] = {0, 0, 0, 0, 0};
    for (int j = 0; j < m; ++j) {
        unsigned long long kj = skey[w][j];
        #pragma unroll
        for (int c = 0; c < 5; ++c) rk2[c] += (kj > fk[c]);
    }
    #pragma unroll
    for (int c = 0; c < 5; ++c) {
        if (c < mc2 && rk2[c] < TOPK_) {
            seli[w][rk2[c]] = 2047 - (int)(fk[c] & 0xFFFFFFFFull);
            selv[w][rk2[c]] = s2f((unsigned)(fk[c] >> 32));
        }
    }
    __syncwarp();

    // ---- output ----
    float a0 = 0.0f, a1 = 0.0f;
    #pragma unroll
    for (int j = 0; j < TOPK_; ++j) {
        float vv = selv[w][j];
        const float* vrow = vb + (size_t)seli[w][j] * D_;
        a0 = fmaf(vv, vrow[lane], a0);
        a1 = fmaf(vv, vrow[lane + 32], a1);
    }
    out[(size_t)r * D_ + lane]      = a0;
    out[(size_t)r * D_ + lane + 32] = a1;
}

// ---------------------------------------------------------------------------
extern "C" void kernel_launch(void* const* d_in, const int* in_sizes, int n_in,
                              void* d_out, int out_size)
{
    const float* q = (const float*)d_in[0];
    const float* k = (const float*)d_in[1];
    const float* v = (const float*)d_in[2];
    float* out = (float*)d_out;

    convert_k<<<(B_ * L_ * D_ / 4) / 256, 256>>>(k);

    cudaFuncSetAttribute(score_harvest,
                         cudaFuncAttributeMaxDynamicSharedMemorySize, SMEM_A);
    score_harvest<<<NBLK, 256, SMEM_A>>>(q);

    select_rows<<<B_ * L_ / 8, 256>>>(q, k, v, out);
}

// round 13
// speedup vs baseline: 1.4704x; 1.0370x over previous
#include <cuda_runtime.h>
#include <cuda_bf16.h>
#include <cstdint>

// Problem constants
#define B_    8
#define L_    2048
#define D_    64
#define TOPK_ 32

// Tiling
#define TQ     32
#define CK     128
#define NCHUNK (L_ / CK)         // 16
#define NBLK   (B_ * L_ / TQ)    // 512
#define BPB    (L_ / TQ)         // 64

// Selection: analytic threshold tau = Z_TAU * ||q|| / 8
#define Z_TAU 1.70f
#define MINC  40
#define CAP   144
#define CAPG  160
#define TRIM  40

#define KST  72                  // Kbf smem row stride (bf16 elems)

// ---- dynamic smem layout (bytes) ----
#define OFF_KBF   0              // bf16 [2][128][72] = 36864  (overlaid post-loop)
#define OFF_QS    36864          // f32  [32][68]     =  8704
#define OFF_TAU   45568          // f32  [32]
#define OFF_CNT   45696          // int  [32]
#define SMEM_A    45824          // x4 blocks/SM

// selection overlays on the KBF region (valid only after mainloop)
#define OFF_PK    0              // u32 [32][144] = 18432 (also selv/seli per row)
#define OFF_IDS   18432          // u16 [32][40]  =  2560
#define OFF_SKEY  20992          // u64 [32][40]  = 10240   (8B aligned)

// Global scratch
__device__ __nv_bfloat16 gKbf[(size_t)B_ * L_ * D_];      // 2 MB
__device__ unsigned g_cand[(size_t)B_ * L_ * CAPG];       // packed (s16<<16)|idx

__device__ __forceinline__ unsigned f2sortable(float f) {
    unsigned bb = __float_as_uint(f);
    return (bb & 0x80000000u) ? ~bb : (bb | 0x80000000u);
}
__device__ __forceinline__ float s2f(unsigned u) {
    unsigned bb = (u & 0x80000000u) ? (u & 0x7FFFFFFFu) : ~u;
    return __uint_as_float(bb);
}
__device__ __forceinline__ unsigned short f2s16(float f) {
    unsigned short b = __bfloat16_as_ushort(__float2bfloat16(f));
    return (b & 0x8000) ? (unsigned short)~b : (unsigned short)(b | 0x8000);
}
__device__ __forceinline__ uint32_t pack_bf2(float lo, float hi) {
    __nv_bfloat162 h2 = __floats2bfloat162_rn(lo, hi);
    return *reinterpret_cast<uint32_t*>(&h2);
}

__device__ __forceinline__ void mma_bf16(
    float& c0, float& c1, float& c2, float& c3,
    uint32_t a0, uint32_t a1, uint32_t a2, uint32_t a3,
    uint32_t b0, uint32_t b1)
{
    asm volatile(
        "mma.sync.aligned.m16n8k16.row.col.f32.bf16.bf16.f32 "
        "{%0,%1,%2,%3}, {%4,%5,%6,%7}, {%8,%9}, {%0,%1,%2,%3};\n"
        : "+f"(c0), "+f"(c1), "+f"(c2), "+f"(c3)
        : "r"(a0), "r"(a1), "r"(a2), "r"(a3), "r"(b0), "r"(b1));
}

__device__ __forceinline__ void cp_async16(uint32_t smem_dst, const void* gsrc) {
    asm volatile("cp.async.cg.shared.global [%0], [%1], 16;\n"
                 :: "r"(smem_dst), "l"(gsrc));
}
__device__ __forceinline__ void cp_commit() {
    asm volatile("cp.async.commit_group;\n");
}
template <int N>
__device__ __forceinline__ void cp_wait() {
    asm volatile("cp.async.wait_group %0;\n" :: "n"(N));
}

// ---------------------------------------------------------------------------
// Kernel 0: K fp32 -> bf16
// ---------------------------------------------------------------------------
__global__ __launch_bounds__(256) void convert_k(const float* __restrict__ k) {
    int idx = blockIdx.x * 256 + threadIdx.x;
    float4 kv = *(const float4*)(k + (size_t)idx * 4);
    uint2 o;
    o.x = pack_bf2(kv.x, kv.y);
    o.y = pack_bf2(kv.z, kv.w);
    *(uint2*)((unsigned short*)gKbf + (size_t)idx * 4) = o;
}

// ---------------------------------------------------------------------------
// Fused: HMMA score + threshold harvest + trim + rescore + top-32 + output
// ---------------------------------------------------------------------------
__global__ __launch_bounds__(256, 4) void fused_attn(
    const float* __restrict__ q, const float* __restrict__ k,
    const float* __restrict__ v, float* __restrict__ out)
{
    extern __shared__ __align__(16) char smem[];
    unsigned short* Kbf = (unsigned short*)(smem + OFF_KBF);
    float* Qs   = (float*)(smem + OFF_QS);
    float* tauA = (float*)(smem + OFF_TAU);
    int*   cnt  = (int*)(smem + OFF_CNT);

    const int t    = threadIdx.x;
    const int lane = t & 31;
    const int w    = t >> 5;
    const unsigned full = 0xffffffffu;
    const unsigned ltmask = (1u << lane) - 1u;

    const int rowBase = blockIdx.x * TQ;
    const int b       = blockIdx.x / BPB;
    const float* kb   = k + (size_t)b * L_ * D_;
    const float* vb   = v + (size_t)b * L_ * D_;
    const __nv_bfloat16* gkb = gKbf + (size_t)b * L_ * D_;
    const uint32_t ksBase = (uint32_t)__cvta_generic_to_shared(Kbf);

    for (int i = t; i < TQ * 16; i += 256) {
        int row = i >> 4, dg4 = (i & 15) << 2;
        *(float4*)(Qs + row * 68 + dg4) =
            *(const float4*)(q + ((size_t)(rowBase + row)) * D_ + dg4);
    }
    if (t < TQ) cnt[t] = 0;
    __syncthreads();

    // per-row analytic tau (warp w -> rows 4w..4w+3)
    for (int rr = 0; rr < 4; ++rr) {
        int row = w * 4 + rr;
        float x = Qs[row * 68 + lane], y = Qs[row * 68 + lane + 32];
        float nrm = x * x + y * y;
        #pragma unroll
        for (int o = 16; o >= 1; o >>= 1) nrm += __shfl_xor_sync(full, nrm, o);
        if (lane == 0) tauA[row] = Z_TAU * sqrtf(nrm) * 0.125f;
    }

    // A fragments (Q) once
    const int rg = w >> 2;
    const int ns = w & 3;
    const int ar = rg * 16 + (lane >> 2);
    const int ac = (lane & 3) * 2;
    uint32_t afr[4][4];
    #pragma unroll
    for (int ks = 0; ks < 4; ++ks) {
        int col = ks * 16 + ac;
        afr[ks][0] = pack_bf2(Qs[ar * 68 + col],           Qs[ar * 68 + col + 1]);
        afr[ks][1] = pack_bf2(Qs[(ar + 8) * 68 + col],     Qs[(ar + 8) * 68 + col + 1]);
        afr[ks][2] = pack_bf2(Qs[ar * 68 + col + 8],       Qs[ar * 68 + col + 9]);
        afr[ks][3] = pack_bf2(Qs[(ar + 8) * 68 + col + 8], Qs[(ar + 8) * 68 + col + 9]);
    }

    // prologue chunk 0
    #pragma unroll
    for (int g = 0; g < 4; ++g) {
        int seg = g * 256 + t;
        int key = seg >> 3, o = seg & 7;
        cp_async16(ksBase + (uint32_t)(key * 144 + o * 16),
                   gkb + (size_t)key * D_ + o * 8);
    }
    cp_commit();
    __syncthreads();

    unsigned* candRowA = g_cand + (size_t)(rowBase + ar) * CAPG;
    unsigned* candRowB = g_cand + (size_t)(rowBase + ar + 8) * CAPG;

    for (int chunk = 0; chunk < NCHUNK; ++chunk) {
        if (chunk + 1 < NCHUNK) {
            const int keyNext = (chunk + 1) * CK;
            const uint32_t dstB = ksBase + ((chunk + 1) & 1) * 18432;
            #pragma unroll
            for (int g = 0; g < 4; ++g) {
                int seg = g * 256 + t;
                int key = seg >> 3, o = seg & 7;
                cp_async16(dstB + (uint32_t)(key * 144 + o * 16),
                           gkb + (size_t)(keyNext + key) * D_ + o * 8);
            }
            cp_commit();
            cp_wait<1>();
        } else {
            cp_wait<0>();
        }
        __syncthreads();

        const unsigned short* Kb = Kbf + (chunk & 1) * (CK * KST);
        const float tau_a = tauA[ar], tau_b = tauA[ar + 8];
        #pragma unroll
        for (int nt = 0; nt < 4; ++nt) {
            const int keyInChunk = ns * 32 + nt * 8 + (lane >> 2);
            float c0 = 0.f, c1 = 0.f, c2 = 0.f, c3 = 0.f;
            #pragma unroll
            for (int ks = 0; ks < 4; ++ks) {
                int col = ks * 16 + ac;
                uint32_t b0 = *(const uint32_t*)&Kb[keyInChunk * KST + col];
                uint32_t b1 = *(const uint32_t*)&Kb[keyInChunk * KST + col + 8];
                mma_bf16(c0, c1, c2, c3,
                         afr[ks][0], afr[ks][1], afr[ks][2], afr[ks][3], b0, b1);
            }
            const unsigned kcol = chunk * CK + ns * 32 + nt * 8 + ac;
            c0 *= 0.125f; c1 *= 0.125f; c2 *= 0.125f; c3 *= 0.125f;
            if (c0 >= tau_a) { int p = atomicAdd(&cnt[ar], 1);     if (p < CAP) candRowA[p] = ((unsigned)f2s16(c0) << 16) | kcol; }
            if (c1 >= tau_a) { int p = atomicAdd(&cnt[ar], 1);     if (p < CAP) candRowA[p] = ((unsigned)f2s16(c1) << 16) | (kcol + 1); }
            if (c2 >= tau_b) { int p = atomicAdd(&cnt[ar + 8], 1); if (p < CAP) candRowB[p] = ((unsigned)f2s16(c2) << 16) | kcol; }
            if (c3 >= tau_b) { int p = atomicAdd(&cnt[ar + 8], 1); if (p < CAP) candRowB[p] = ((unsigned)f2s16(c3) << 16) | (kcol + 1); }
        }
        __syncthreads();
    }
    // mainloop done; Kbf region is dead -> overlay selection arrays

    unsigned* pkA = (unsigned*)(smem + OFF_PK);
    unsigned short* idsA = (unsigned short*)(smem + OFF_IDS);
    unsigned long long* skA = (unsigned long long*)(smem + OFF_SKEY);

    for (int rr = 0; rr < 4; ++rr) {
        const int row  = w * 4 + rr;
        const int grow = rowBase + row;
        const float* qrow = Qs + row * 68;
        unsigned* pk = pkA + row * CAP;
        unsigned short* ids = idsA + row * TRIM;
        unsigned long long* skey = skA + row * TRIM;

        int n = cnt[row];
        const bool fb = (n < MINC || n > CAP);

        if (!fb) {
            const unsigned* candRow = g_cand + (size_t)grow * CAPG;
            for (int i = lane; i < n; i += 32) pk[i] = candRow[i];
        } else {
            // rare fallback: bisection threshold over recomputed bf16 scores,
            // then rebuild packed candidates into pk
            float nx = qrow[lane], ny = qrow[lane + 32];
            float nrm = nx * nx + ny * ny;
            #pragma unroll
            for (int o = 16; o >= 1; o >>= 1) nrm += __shfl_xor_sync(full, nrm, o);
            unsigned lo = 0u, hi = 0xFFFFFFFFu;
            unsigned mid = f2sortable(Z_TAU * sqrtf(nrm) * 0.125f), tu = 0u;
            bool have = false;
            for (int it = 0; it < 34; ++it) {
                int c = 0;
                for (int j = 0; j < 64; ++j) {
                    const float4* k4 = (const float4*)(kb + (size_t)(j * 32 + lane) * D_);
                    float s = 0.0f;
                    #pragma unroll
                    for (int dg = 0; dg < 16; ++dg) {
                        float4 kv = k4[dg];
                        s = fmaf(qrow[dg * 4],     kv.x, s);
                        s = fmaf(qrow[dg * 4 + 1], kv.y, s);
                        s = fmaf(qrow[dg * 4 + 2], kv.z, s);
                        s = fmaf(qrow[dg * 4 + 3], kv.w, s);
                    }
                    c += (f2sortable(s * 0.125f) >= mid);
                }
                #pragma unroll
                for (int o = 16; o >= 1; o >>= 1) c += __shfl_xor_sync(full, c, o);
                if (c >= MINC && c <= CAP) { tu = mid; have = true; break; }
                if (c < MINC) hi = mid; else { lo = mid; tu = mid; have = true; }
                mid = lo + ((hi - lo) >> 1);
                if (mid == lo) { if (!have) tu = lo; break; }
            }
            int base = 0;
            for (int j = 0; j < 64; ++j) {
                int key = j * 32 + lane;
                const float4* k4 = (const float4*)(kb + (size_t)key * D_);
                float s = 0.0f;
                #pragma unroll
                for (int dg = 0; dg < 16; ++dg) {
                    float4 kv = k4[dg];
                    s = fmaf(qrow[dg * 4],     kv.x, s);
                    s = fmaf(qrow[dg * 4 + 1], kv.y, s);
                    s = fmaf(qrow[dg * 4 + 2], kv.z, s);
                    s = fmaf(qrow[dg * 4 + 3], kv.w, s);
                }
                s *= 0.125f;
                bool cnd = f2sortable(s) >= tu;
                unsigned mk = __ballot_sync(full, cnd);
                if (cnd) {
                    int pos = base + __popc(mk & ltmask);
                    if (pos < CAP) pk[pos] = ((unsigned)f2s16(s) << 16) | (unsigned)key;
                }
                base += __popc(mk);
            }
            n = base < CAP ? base : CAP;
        }
        __syncwarp();

        // ---- trim: keep packed-rank < TRIM ----
        unsigned mp[5];
        int mc = 0;
        for (int i = lane; i < n; i += 32) mp[mc++] = pk[i];
        int rk[5] = {0, 0, 0, 0, 0};
        for (int j = 0; j < n; ++j) {
            unsigned pj = pk[j];
            #pragma unroll
            for (int c = 0; c < 5; ++c) rk[c] += (pj > mp[c]);
        }
        int base2 = 0;
        #pragma unroll
        for (int c = 0; c < 5; ++c) {
            bool sv = (c < mc) && (rk[c] < TRIM);
            unsigned msk = __ballot_sync(full, sv);
            if (sv) {
                int pos = base2 + __popc(msk & ltmask);
                ids[pos] = (unsigned short)(mp[c] & 0xFFFFu);
            }
            base2 += __popc(msk);
        }
        const int m = base2;                 // = min(n, TRIM) <= 40
        __syncwarp();

        // ---- cooperative fp32 rescore: 4-lane groups, full 32B sectors ----
        const int g4 = lane >> 2, l4 = lane & 3;
        for (int i = 0; i < m; i += 8) {
            int slot = i + g4;
            float s = 0.0f;
            int idx = 0;
            if (slot < m) {
                idx = ids[slot];
                const float4* kr = (const float4*)(kb + (size_t)idx * D_);
                #pragma unroll
                for (int j = 0; j < 4; ++j) {
                    float4 kv = kr[l4 + j * 4];
                    const float* qq = qrow + l4 * 4 + j * 16;
                    s = fmaf(qq[0], kv.x, s); s = fmaf(qq[1], kv.y, s);
                    s = fmaf(qq[2], kv.z, s); s = fmaf(qq[3], kv.w, s);
                }
            }
            s += __shfl_xor_sync(full, s, 1);
            s += __shfl_xor_sync(full, s, 2);
            if (slot < m && l4 == 0) {
                s *= 0.125f;
                skey[slot] = ((unsigned long long)f2sortable(s) << 32)
                           | (unsigned)(2047 - idx);
            }
        }
        __syncwarp();

        // ---- exact top-32 among m (u64: val desc, tie -> lower idx) ----
        float* selv = (float*)pk;            // reuse pk row area (trim done)
        int*   seli = (int*)(pk + 32);
        unsigned long long fk[2] = {0ull, 0ull};
        int mc2 = 0;
        for (int i = lane; i < m; i += 32) fk[mc2++] = skey[i];
        int rk2[2] = {0, 0};
        for (int j = 0; j < m; ++j) {
            unsigned long long kj = skey[j];
            rk2[0] += (kj > fk[0]);
            rk2[1] += (kj > fk[1]);
        }
        #pragma unroll
        for (int c = 0; c < 2; ++c) {
            if (c < mc2 && rk2[c] < TOPK_) {
                seli[rk2[c]] = 2047 - (int)(fk[c] & 0xFFFFFFFFull);
                selv[rk2[c]] = s2f((unsigned)(fk[c] >> 32));
            }
        }
        __syncwarp();

        // ---- output ----
        float a0 = 0.0f, a1 = 0.0f;
        #pragma unroll
        for (int j = 0; j < TOPK_; ++j) {
            float vv = selv[j];
            const float* vrow = vb + (size_t)seli[j] * D_;
            a0 = fmaf(vv, vrow[lane], a0);
            a1 = fmaf(vv, vrow[lane + 32], a1);
        }
        out[(size_t)grow * D_ + lane]      = a0;
        out[(size_t)grow * D_ + lane + 32] = a1;
        __syncwarp();
    }
}

// ---------------------------------------------------------------------------
extern "C" void kernel_launch(void* const* d_in, const int* in_sizes, int n_in,
                              void* d_out, int out_size)
{
    const float* q = (const float*)d_in[0];
    const float* k = (const float*)d_in[1];
    const float* v = (const float*)d_in[2];
    float* out = (float*)d_out;

    convert_k<<<(B_ * L_ * D_ / 4) / 256, 256>>>(k);

    cudaFuncSetAttribute(fused_attn,
                         cudaFuncAttributeMaxDynamicSharedMemorySize, SMEM_A);
    fused_attn<<<NBLK, 256, SMEM_A>>>(q, k, v, out);
}

// round 14
// speedup vs baseline: 1.5893x; 1.0809x over previous
#include <cuda_runtime.h>
#include <cuda_bf16.h>
#include <cstdint>

// Problem constants
#define B_    8
#define L_    2048
#define D_    64
#define TOPK_ 32

// Tiling
#define TQ     32
#define CK     128
#define NCHUNK (L_ / CK)         // 16
#define NBLK   (B_ * L_ / TQ)    // 512
#define BPB    (L_ / TQ)         // 64

// Selection: analytic threshold tau = Z_TAU * ||q|| / 8
#define Z_TAU 1.70f
#define MINC  40
#define CAP   144
#define CAPG  160
#define TRIM  40

#define KST  72                  // Kbf smem row stride (bf16 elems)

// ---- dynamic smem layout (bytes) ----
#define OFF_KBF   0              // bf16 [2][128][72] = 36864  (overlaid post-loop)
#define OFF_QS    36864          // f32  [32][68]     =  8704
#define OFF_TAU   45568          // f32  [32]  (stores tau*8 = Z*||q||)
#define OFF_CNT   45696          // int  [32]
#define SMEM_A    45824          // x4 blocks/SM

// selection overlays on the KBF region (valid only after mainloop)
#define OFF_PK    0              // u32 [32][144] = 18432 (also selv/seli per row)
#define OFF_IDS   18432          // u16 [32][40]  =  2560
#define OFF_SKEY  20992          // u64 [32][40]  = 10240

// Global scratch
__device__ __nv_bfloat16 gKbf[(size_t)B_ * L_ * D_];      // 2 MB
__device__ unsigned g_cand[(size_t)B_ * L_ * CAPG];       // packed (s16<<16)|idx

__device__ __forceinline__ unsigned f2sortable(float f) {
    unsigned bb = __float_as_uint(f);
    return (bb & 0x80000000u) ? ~bb : (bb | 0x80000000u);
}
__device__ __forceinline__ float s2f(unsigned u) {
    unsigned bb = (u & 0x80000000u) ? (u & 0x7FFFFFFFu) : ~u;
    return __uint_as_float(bb);
}
__device__ __forceinline__ unsigned short f2s16(float f) {
    unsigned short b = __bfloat16_as_ushort(__float2bfloat16(f));
    return (b & 0x8000) ? (unsigned short)~b : (unsigned short)(b | 0x8000);
}
__device__ __forceinline__ uint32_t pack_bf2(float lo, float hi) {
    __nv_bfloat162 h2 = __floats2bfloat162_rn(lo, hi);
    return *reinterpret_cast<uint32_t*>(&h2);
}

__device__ __forceinline__ void mma_bf16(
    float& c0, float& c1, float& c2, float& c3,
    uint32_t a0, uint32_t a1, uint32_t a2, uint32_t a3,
    uint32_t b0, uint32_t b1)
{
    asm volatile(
        "mma.sync.aligned.m16n8k16.row.col.f32.bf16.bf16.f32 "
        "{%0,%1,%2,%3}, {%4,%5,%6,%7}, {%8,%9}, {%0,%1,%2,%3};\n"
        : "+f"(c0), "+f"(c1), "+f"(c2), "+f"(c3)
        : "r"(a0), "r"(a1), "r"(a2), "r"(a3), "r"(b0), "r"(b1));
}

__device__ __forceinline__ void cp_async16(uint32_t smem_dst, const void* gsrc) {
    asm volatile("cp.async.cg.shared.global [%0], [%1], 16;\n"
                 :: "r"(smem_dst), "l"(gsrc));
}
__device__ __forceinline__ void cp_commit() {
    asm volatile("cp.async.commit_group;\n");
}
template <int N>
__device__ __forceinline__ void cp_wait() {
    asm volatile("cp.async.wait_group %0;\n" :: "n"(N));
}

// ---------------------------------------------------------------------------
// Kernel 0: K fp32 -> bf16
// ---------------------------------------------------------------------------
__global__ __launch_bounds__(256) void convert_k(const float* __restrict__ k) {
    int idx = blockIdx.x * 256 + threadIdx.x;
    float4 kv = *(const float4*)(k + (size_t)idx * 4);
    uint2 o;
    o.x = pack_bf2(kv.x, kv.y);
    o.y = pack_bf2(kv.z, kv.w);
    *(uint2*)((unsigned short*)gKbf + (size_t)idx * 4) = o;
}

// ---------------------------------------------------------------------------
// Fused: HMMA score + threshold harvest + trim + rescore + top-32 + output
// ---------------------------------------------------------------------------
__global__ __launch_bounds__(256, 4) void fused_attn(
    const float* __restrict__ q, const float* __restrict__ k,
    const float* __restrict__ v, float* __restrict__ out)
{
    extern __shared__ __align__(16) char smem[];
    unsigned short* Kbf = (unsigned short*)(smem + OFF_KBF);
    float* Qs   = (float*)(smem + OFF_QS);
    float* tauA = (float*)(smem + OFF_TAU);   // tau*8 = Z*||q||
    int*   cnt  = (int*)(smem + OFF_CNT);

    const int t    = threadIdx.x;
    const int lane = t & 31;
    const int w    = t >> 5;
    const unsigned full = 0xffffffffu;
    const unsigned ltmask = (1u << lane) - 1u;

    const int rowBase = blockIdx.x * TQ;
    const int b       = blockIdx.x / BPB;
    const float* kb   = k + (size_t)b * L_ * D_;
    const float* vb   = v + (size_t)b * L_ * D_;
    const __nv_bfloat16* gkb = gKbf + (size_t)b * L_ * D_;
    const uint32_t ksBase = (uint32_t)__cvta_generic_to_shared(Kbf);

    for (int i = t; i < TQ * 16; i += 256) {
        int row = i >> 4, dg4 = (i & 15) << 2;
        *(float4*)(Qs + row * 68 + dg4) =
            *(const float4*)(q + ((size_t)(rowBase + row)) * D_ + dg4);
    }
    if (t < TQ) cnt[t] = 0;
    __syncthreads();

    // per-row analytic tau*8 (warp w -> rows 4w..4w+3)
    for (int rr = 0; rr < 4; ++rr) {
        int row = w * 4 + rr;
        float x = Qs[row * 68 + lane], y = Qs[row * 68 + lane + 32];
        float nrm = x * x + y * y;
        #pragma unroll
        for (int o = 16; o >= 1; o >>= 1) nrm += __shfl_xor_sync(full, nrm, o);
        if (lane == 0) tauA[row] = Z_TAU * sqrtf(nrm);    // raw-score threshold
    }

    // A fragments (Q) once
    const int rg = w >> 2;
    const int ns = w & 3;
    const int ar = rg * 16 + (lane >> 2);
    const int ac = (lane & 3) * 2;
    uint32_t afr[4][4];
    #pragma unroll
    for (int ks = 0; ks < 4; ++ks) {
        int col = ks * 16 + ac;
        afr[ks][0] = pack_bf2(Qs[ar * 68 + col],           Qs[ar * 68 + col + 1]);
        afr[ks][1] = pack_bf2(Qs[(ar + 8) * 68 + col],     Qs[(ar + 8) * 68 + col + 1]);
        afr[ks][2] = pack_bf2(Qs[ar * 68 + col + 8],       Qs[ar * 68 + col + 9]);
        afr[ks][3] = pack_bf2(Qs[(ar + 8) * 68 + col + 8], Qs[(ar + 8) * 68 + col + 9]);
    }

    // prologue chunk 0
    #pragma unroll
    for (int g = 0; g < 4; ++g) {
        int seg = g * 256 + t;
        int key = seg >> 3, o = seg & 7;
        cp_async16(ksBase + (uint32_t)(key * 144 + o * 16),
                   gkb + (size_t)key * D_ + o * 8);
    }
    cp_commit();
    __syncthreads();

    unsigned* candRowA = g_cand + (size_t)(rowBase + ar) * CAPG;
    unsigned* candRowB = g_cand + (size_t)(rowBase + ar + 8) * CAPG;

    for (int chunk = 0; chunk < NCHUNK; ++chunk) {
        if (chunk + 1 < NCHUNK) {
            const int keyNext = (chunk + 1) * CK;
            const uint32_t dstB = ksBase + ((chunk + 1) & 1) * 18432;
            #pragma unroll
            for (int g = 0; g < 4; ++g) {
                int seg = g * 256 + t;
                int key = seg >> 3, o = seg & 7;
                cp_async16(dstB + (uint32_t)(key * 144 + o * 16),
                           gkb + (size_t)(keyNext + key) * D_ + o * 8);
            }
            cp_commit();
            cp_wait<1>();
        } else {
            cp_wait<0>();
        }
        __syncthreads();

        const unsigned short* Kb = Kbf + (chunk & 1) * (CK * KST);
        const float tau_a = tauA[ar], tau_b = tauA[ar + 8];
        #pragma unroll
        for (int nt = 0; nt < 4; ++nt) {
            const int keyInChunk = ns * 32 + nt * 8 + (lane >> 2);
            float c0 = 0.f, c1 = 0.f, c2 = 0.f, c3 = 0.f;
            #pragma unroll
            for (int ks = 0; ks < 4; ++ks) {
                int col = ks * 16 + ac;
                uint32_t b0 = *(const uint32_t*)&Kb[keyInChunk * KST + col];
                uint32_t b1 = *(const uint32_t*)&Kb[keyInChunk * KST + col + 8];
                mma_bf16(c0, c1, c2, c3,
                         afr[ks][0], afr[ks][1], afr[ks][2], afr[ks][3], b0, b1);
            }
            const unsigned kcol = chunk * CK + ns * 32 + nt * 8 + ac;
            // raw-score compare; scale + pack only for the rare candidates
            if (c0 >= tau_a) { float s = c0 * 0.125f; int p = atomicAdd(&cnt[ar], 1);     if (p < CAP) candRowA[p] = ((unsigned)f2s16(s) << 16) | kcol; }
            if (c1 >= tau_a) { float s = c1 * 0.125f; int p = atomicAdd(&cnt[ar], 1);     if (p < CAP) candRowA[p] = ((unsigned)f2s16(s) << 16) | (kcol + 1); }
            if (c2 >= tau_b) { float s = c2 * 0.125f; int p = atomicAdd(&cnt[ar + 8], 1); if (p < CAP) candRowB[p] = ((unsigned)f2s16(s) << 16) | kcol; }
            if (c3 >= tau_b) { float s = c3 * 0.125f; int p = atomicAdd(&cnt[ar + 8], 1); if (p < CAP) candRowB[p] = ((unsigned)f2s16(s) << 16) | (kcol + 1); }
        }
        __syncthreads();
    }
    // mainloop done; Kbf region is dead -> overlay selection arrays

    unsigned* pkA = (unsigned*)(smem + OFF_PK);
    unsigned short* idsA = (unsigned short*)(smem + OFF_IDS);
    unsigned long long* skA = (unsigned long long*)(smem + OFF_SKEY);

    for (int rr = 0; rr < 4; ++rr) {
        const int row  = w * 4 + rr;
        const int grow = rowBase + row;
        const float* qrow = Qs + row * 68;
        unsigned* pk = pkA + row * CAP;
        unsigned short* ids = idsA + row * TRIM;
        unsigned long long* skey = skA + row * TRIM;

        int n = cnt[row];
        const bool fb = (n < MINC || n > CAP);

        if (!fb) {
            const unsigned* candRow = g_cand + (size_t)grow * CAPG;
            for (int i = lane; i < n; i += 32) pk[i] = candRow[i];
        } else {
            // rare fallback: bisection threshold over recomputed fp32 scores
            float nx = qrow[lane], ny = qrow[lane + 32];
            float nrm = nx * nx + ny * ny;
            #pragma unroll
            for (int o = 16; o >= 1; o >>= 1) nrm += __shfl_xor_sync(full, nrm, o);
            unsigned lo = 0u, hi = 0xFFFFFFFFu;
            unsigned mid = f2sortable(Z_TAU * sqrtf(nrm) * 0.125f), tu = 0u;
            bool have = false;
            for (int it = 0; it < 34; ++it) {
                int c = 0;
                for (int j = 0; j < 64; ++j) {
                    const float4* k4 = (const float4*)(kb + (size_t)(j * 32 + lane) * D_);
                    float s = 0.0f;
                    #pragma unroll
                    for (int dg = 0; dg < 16; ++dg) {
                        float4 kv = k4[dg];
                        s = fmaf(qrow[dg * 4],     kv.x, s);
                        s = fmaf(qrow[dg * 4 + 1], kv.y, s);
                        s = fmaf(qrow[dg * 4 + 2], kv.z, s);
                        s = fmaf(qrow[dg * 4 + 3], kv.w, s);
                    }
                    c += (f2sortable(s * 0.125f) >= mid);
                }
                #pragma unroll
                for (int o = 16; o >= 1; o >>= 1) c += __shfl_xor_sync(full, c, o);
                if (c >= MINC && c <= CAP) { tu = mid; have = true; break; }
                if (c < MINC) hi = mid; else { lo = mid; tu = mid; have = true; }
                mid = lo + ((hi - lo) >> 1);
                if (mid == lo) { if (!have) tu = lo; break; }
            }
            int base = 0;
            for (int j = 0; j < 64; ++j) {
                int key = j * 32 + lane;
                const float4* k4 = (const float4*)(kb + (size_t)key * D_);
                float s = 0.0f;
                #pragma unroll
                for (int dg = 0; dg < 16; ++dg) {
                    float4 kv = k4[dg];
                    s = fmaf(qrow[dg * 4],     kv.x, s);
                    s = fmaf(qrow[dg * 4 + 1], kv.y, s);
                    s = fmaf(qrow[dg * 4 + 2], kv.z, s);
                    s = fmaf(qrow[dg * 4 + 3], kv.w, s);
                }
                s *= 0.125f;
                bool cnd = f2sortable(s) >= tu;
                unsigned mk = __ballot_sync(full, cnd);
                if (cnd) {
                    int pos = base + __popc(mk & ltmask);
                    if (pos < CAP) pk[pos] = ((unsigned)f2s16(s) << 16) | (unsigned)key;
                }
                base += __popc(mk);
            }
            n = base < CAP ? base : CAP;
        }
        __syncwarp();

        // ---- trim: keep packed-rank < TRIM (3-wide fast path for n<=96) ----
        unsigned mp[5];
        int mc = 0;
        for (int i = lane; i < n; i += 32) mp[mc++] = pk[i];
        int rk[5] = {0, 0, 0, 0, 0};
        if (n <= 96) {
            for (int j = 0; j < n; ++j) {
                unsigned pj = pk[j];
                rk[0] += (pj > mp[0]);
                rk[1] += (pj > mp[1]);
                rk[2] += (pj > mp[2]);
            }
        } else {
            for (int j = 0; j < n; ++j) {
                unsigned pj = pk[j];
                #pragma unroll
                for (int c = 0; c < 5; ++c) rk[c] += (pj > mp[c]);
            }
        }
        int base2 = 0;
        #pragma unroll
        for (int c = 0; c < 5; ++c) {
            bool sv = (c < mc) && (rk[c] < TRIM);
            unsigned msk = __ballot_sync(full, sv);
            if (sv) {
                int pos = base2 + __popc(msk & ltmask);
                ids[pos] = (unsigned short)(mp[c] & 0xFFFFu);
            }
            base2 += __popc(msk);
        }
        const int m = base2;                 // = min(n, TRIM) <= 40
        __syncwarp();

        // ---- cooperative fp32 rescore: 4-lane groups, full 32B sectors ----
        const int g4 = lane >> 2, l4 = lane & 3;
        for (int i = 0; i < m; i += 8) {
            int slot = i + g4;
            float s = 0.0f;
            int idx = 0;
            if (slot < m) {
                idx = ids[slot];
                const float4* kr = (const float4*)(kb + (size_t)idx * D_);
                #pragma unroll
                for (int j = 0; j < 4; ++j) {
                    float4 kv = kr[l4 + j * 4];
                    const float* qq = qrow + l4 * 4 + j * 16;
                    s = fmaf(qq[0], kv.x, s); s = fmaf(qq[1], kv.y, s);
                    s = fmaf(qq[2], kv.z, s); s = fmaf(qq[3], kv.w, s);
                }
            }
            s += __shfl_xor_sync(full, s, 1);
            s += __shfl_xor_sync(full, s, 2);
            if (slot < m && l4 == 0) {
                s *= 0.125f;
                skey[slot] = ((unsigned long long)f2sortable(s) << 32)
                           | (unsigned)(2047 - idx);
            }
        }
        __syncwarp();

        // ---- exact top-32 among m (u64: val desc, tie -> lower idx) ----
        float* selv = (float*)pk;            // reuse pk row area (trim done)
        int*   seli = (int*)(pk + 32);
        unsigned long long fk[2] = {0ull, 0ull};
        int mc2 = 0;
        for (int i = lane; i < m; i += 32) fk[mc2++] = skey[i];
        int rk2[2] = {0, 0};
        for (int j = 0; j < m; ++j) {
            unsigned long long kj = skey[j];
            rk2[0] += (kj > fk[0]);
            rk2[1] += (kj > fk[1]);
        }
        #pragma unroll
        for (int c = 0; c < 2; ++c) {
            if (c < mc2 && rk2[c] < TOPK_) {
                seli[rk2[c]] = 2047 - (int)(fk[c] & 0xFFFFFFFFull);
                selv[rk2[c]] = s2f((unsigned)(fk[c] >> 32));
            }
        }
        __syncwarp();

        // ---- output ----
        float a0 = 0.0f, a1 = 0.0f;
        #pragma unroll
        for (int j = 0; j < TOPK_; ++j) {
            float vv = selv[j];
            const float* vrow = vb + (size_t)seli[j] * D_;
            a0 = fmaf(vv, vrow[lane], a0);
            a1 = fmaf(vv, vrow[lane + 32], a1);
        }
        out[(size_t)grow * D_ + lane]      = a0;
        out[(size_t)grow * D_ + lane + 32] = a1;
        __syncwarp();
    }
}

// ---------------------------------------------------------------------------
extern "C" void kernel_launch(void* const* d_in, const int* in_sizes, int n_in,
                              void* d_out, int out_size)
{
    const float* q = (const float*)d_in[0];
    const float* k = (const float*)d_in[1];
    const float* v = (const float*)d_in[2];
    float* out = (float*)d_out;

    convert_k<<<(B_ * L_ * D_ / 4) / 256, 256>>>(k);

    cudaFuncSetAttribute(fused_attn,
                         cudaFuncAttributeMaxDynamicSharedMemorySize, SMEM_A);
    fused_attn<<<NBLK, 256, SMEM_A>>>(q, k, v, out);
}

// round 15
// speedup vs baseline: 1.5993x; 1.0063x over previous
#include <cuda_runtime.h>
#include <cuda_bf16.h>
#include <cstdint>

// Problem constants
#define B_    8
#define L_    2048
#define D_    64
#define TOPK_ 32

// Tiling
#define TQ     32
#define CK     128
#define NCHUNK (L_ / CK)         // 16
#define NBLK   (B_ * L_ / TQ)    // 512
#define BPB    (L_ / TQ)         // 64

// Selection: analytic threshold tau = Z_TAU * ||q|| / 8
#define Z_TAU 1.70f
#define MINC  40
#define CAP   144
#define CAPG  160
#define TRIM  40

#define KST  72                  // Kbf smem row stride (bf16 elems) = 144B pitch

// ---- dynamic smem layout (bytes) ----
#define OFF_KBF   0              // bf16 [2][128][72] = 36864  (overlaid post-loop)
#define OFF_QS    36864          // f32  [32][68]     =  8704
#define OFF_TAU   45568          // f32  [32]  (stores tau*8 = Z*||q||)
#define OFF_CNT   45696          // int  [32]
#define SMEM_A    45824          // x4 blocks/SM

// selection overlays on the KBF region (valid only after mainloop)
#define OFF_PK    0              // u32 [32][144] = 18432 (also selv/seli per row)
#define OFF_IDS   18432          // u16 [32][40]  =  2560
#define OFF_SKEY  20992          // u64 [32][40]  = 10240

// Global scratch. gKbf rows are PERMUTED per-key:
//   out elem i = ac_g*16 + ks*4 + j  <->  in d = ks*16 + 2*ac_g + (j&1) + (j>=2)*8
// so lane (ac_g = lane&3) loads its full 16-value B slice as 2 x uint4.
__device__ __nv_bfloat16 gKbf[(size_t)B_ * L_ * D_];      // 2 MB
__device__ unsigned g_cand[(size_t)B_ * L_ * CAPG];       // packed (s16<<16)|idx

__device__ __forceinline__ unsigned f2sortable(float f) {
    unsigned bb = __float_as_uint(f);
    return (bb & 0x80000000u) ? ~bb : (bb | 0x80000000u);
}
__device__ __forceinline__ float s2f(unsigned u) {
    unsigned bb = (u & 0x80000000u) ? (u & 0x7FFFFFFFu) : ~u;
    return __uint_as_float(bb);
}
__device__ __forceinline__ unsigned short f2s16(float f) {
    unsigned short b = __bfloat16_as_ushort(__float2bfloat16(f));
    return (b & 0x8000) ? (unsigned short)~b : (unsigned short)(b | 0x8000);
}
__device__ __forceinline__ uint32_t pack_bf2(float lo, float hi) {
    __nv_bfloat162 h2 = __floats2bfloat162_rn(lo, hi);
    return *reinterpret_cast<uint32_t*>(&h2);
}

__device__ __forceinline__ void mma_bf16(
    float& c0, float& c1, float& c2, float& c3,
    uint32_t a0, uint32_t a1, uint32_t a2, uint32_t a3,
    uint32_t b0, uint32_t b1)
{
    asm volatile(
        "mma.sync.aligned.m16n8k16.row.col.f32.bf16.bf16.f32 "
        "{%0,%1,%2,%3}, {%4,%5,%6,%7}, {%8,%9}, {%0,%1,%2,%3};\n"
        : "+f"(c0), "+f"(c1), "+f"(c2), "+f"(c3)
        : "r"(a0), "r"(a1), "r"(a2), "r"(a3), "r"(b0), "r"(b1));
}

__device__ __forceinline__ void cp_async16(uint32_t smem_dst, const void* gsrc) {
    asm volatile("cp.async.cg.shared.global [%0], [%1], 16;\n"
                 :: "r"(smem_dst), "l"(gsrc));
}
__device__ __forceinline__ void cp_commit() {
    asm volatile("cp.async.commit_group;\n");
}
template <int N>
__device__ __forceinline__ void cp_wait() {
    asm volatile("cp.async.wait_group %0;\n" :: "n"(N));
}

// ---------------------------------------------------------------------------
// Kernel 0: K fp32 -> bf16, PERMUTED rows (see gKbf comment)
// grid: B_*L_*8/256 = 512 blocks; thread handles one 8-elem output segment
// ---------------------------------------------------------------------------
__global__ __launch_bounds__(256) void convert_k(const float* __restrict__ k) {
    int idx = blockIdx.x * 256 + threadIdx.x;
    int row = idx >> 3, seg = idx & 7;
    const float* kr = k + (size_t)row * D_;
    int acg = seg >> 1;              // 0..3
    int ks0 = (seg & 1) * 2;         // ks pair base: 0 or 2
    int ac  = acg * 2;

    uint4 o;
    {
        int base = ks0 * 16 + ac;
        o.x = pack_bf2(kr[base],     kr[base + 1]);   // ks0 b0
        o.y = pack_bf2(kr[base + 8], kr[base + 9]);   // ks0 b1
    }
    {
        int base = (ks0 + 1) * 16 + ac;
        o.z = pack_bf2(kr[base],     kr[base + 1]);   // ks0+1 b0
        o.w = pack_bf2(kr[base + 8], kr[base + 9]);   // ks0+1 b1
    }
    *(uint4*)((unsigned short*)gKbf + (size_t)row * D_ + seg * 8) = o;
}

// ---------------------------------------------------------------------------
// Fused: HMMA score + threshold harvest + trim + rescore + top-32 + output
// ---------------------------------------------------------------------------
__global__ __launch_bounds__(256, 4) void fused_attn(
    const float* __restrict__ q, const float* __restrict__ k,
    const float* __restrict__ v, float* __restrict__ out)
{
    extern __shared__ __align__(16) char smem[];
    unsigned short* Kbf = (unsigned short*)(smem + OFF_KBF);
    float* Qs   = (float*)(smem + OFF_QS);
    float* tauA = (float*)(smem + OFF_TAU);   // tau*8 = Z*||q||
    int*   cnt  = (int*)(smem + OFF_CNT);

    const int t    = threadIdx.x;
    const int lane = t & 31;
    const int w    = t >> 5;
    const unsigned full = 0xffffffffu;
    const unsigned ltmask = (1u << lane) - 1u;

    const int rowBase = blockIdx.x * TQ;
    const int b       = blockIdx.x / BPB;
    const float* kb   = k + (size_t)b * L_ * D_;
    const float* vb   = v + (size_t)b * L_ * D_;
    const __nv_bfloat16* gkb = gKbf + (size_t)b * L_ * D_;
    const uint32_t ksBase = (uint32_t)__cvta_generic_to_shared(Kbf);

    for (int i = t; i < TQ * 16; i += 256) {
        int row = i >> 4, dg4 = (i & 15) << 2;
        *(float4*)(Qs + row * 68 + dg4) =
            *(const float4*)(q + ((size_t)(rowBase + row)) * D_ + dg4);
    }
    if (t < TQ) cnt[t] = 0;
    __syncthreads();

    // per-row analytic tau*8 (warp w -> rows 4w..4w+3)
    for (int rr = 0; rr < 4; ++rr) {
        int row = w * 4 + rr;
        float x = Qs[row * 68 + lane], y = Qs[row * 68 + lane + 32];
        float nrm = x * x + y * y;
        #pragma unroll
        for (int o = 16; o >= 1; o >>= 1) nrm += __shfl_xor_sync(full, nrm, o);
        if (lane == 0) tauA[row] = Z_TAU * sqrtf(nrm);    // raw-score threshold
    }

    // A fragments (Q) once
    const int rg = w >> 2;
    const int ns = w & 3;
    const int qr = lane >> 2;
    const int acg = lane & 3;
    const int ar = rg * 16 + qr;
    const int ac = acg * 2;
    uint32_t afr[4][4];
    #pragma unroll
    for (int ks = 0; ks < 4; ++ks) {
        int col = ks * 16 + ac;
        afr[ks][0] = pack_bf2(Qs[ar * 68 + col],           Qs[ar * 68 + col + 1]);
        afr[ks][1] = pack_bf2(Qs[(ar + 8) * 68 + col],     Qs[(ar + 8) * 68 + col + 1]);
        afr[ks][2] = pack_bf2(Qs[ar * 68 + col + 8],       Qs[ar * 68 + col + 9]);
        afr[ks][3] = pack_bf2(Qs[(ar + 8) * 68 + col + 8], Qs[(ar + 8) * 68 + col + 9]);
    }

    // prologue chunk 0
    #pragma unroll
    for (int g = 0; g < 4; ++g) {
        int seg = g * 256 + t;
        int key = seg >> 3, o = seg & 7;
        cp_async16(ksBase + (uint32_t)(key * 144 + o * 16),
                   gkb + (size_t)key * D_ + o * 8);
    }
    cp_commit();
    __syncthreads();

    unsigned* candRowA = g_cand + (size_t)(rowBase + ar) * CAPG;
    unsigned* candRowB = g_cand + (size_t)(rowBase + ar + 8) * CAPG;

    for (int chunk = 0; chunk < NCHUNK; ++chunk) {
        if (chunk + 1 < NCHUNK) {
            const int keyNext = (chunk + 1) * CK;
            const uint32_t dstB = ksBase + ((chunk + 1) & 1) * 18432;
            #pragma unroll
            for (int g = 0; g < 4; ++g) {
                int seg = g * 256 + t;
                int key = seg >> 3, o = seg & 7;
                cp_async16(dstB + (uint32_t)(key * 144 + o * 16),
                           gkb + (size_t)(keyNext + key) * D_ + o * 8);
            }
            cp_commit();
            cp_wait<1>();
        } else {
            cp_wait<0>();
        }
        __syncthreads();

        const unsigned short* Kb = Kbf + (chunk & 1) * (CK * KST);
        const float tau_a = tauA[ar], tau_b = tauA[ar + 8];
        #pragma unroll
        for (int nt = 0; nt < 4; ++nt) {
            const int keyInChunk = ns * 32 + nt * 8 + qr;
            // permuted layout: this lane's full B slice = 2 x uint4
            const uint4* bp = (const uint4*)&Kb[keyInChunk * KST + acg * 16];
            uint4 bA = bp[0];      // ks0: b0,b1 ; ks1: b0,b1
            uint4 bB = bp[1];      // ks2: b0,b1 ; ks3: b0,b1
            float c0 = 0.f, c1 = 0.f, c2 = 0.f, c3 = 0.f;
            mma_bf16(c0, c1, c2, c3, afr[0][0], afr[0][1], afr[0][2], afr[0][3], bA.x, bA.y);
            mma_bf16(c0, c1, c2, c3, afr[1][0], afr[1][1], afr[1][2], afr[1][3], bA.z, bA.w);
            mma_bf16(c0, c1, c2, c3, afr[2][0], afr[2][1], afr[2][2], afr[2][3], bB.x, bB.y);
            mma_bf16(c0, c1, c2, c3, afr[3][0], afr[3][1], afr[3][2], afr[3][3], bB.z, bB.w);
            const unsigned kcol = chunk * CK + ns * 32 + nt * 8 + ac;
            if (c0 >= tau_a) { float s = c0 * 0.125f; int p = atomicAdd(&cnt[ar], 1);     if (p < CAP) candRowA[p] = ((unsigned)f2s16(s) << 16) | kcol; }
            if (c1 >= tau_a) { float s = c1 * 0.125f; int p = atomicAdd(&cnt[ar], 1);     if (p < CAP) candRowA[p] = ((unsigned)f2s16(s) << 16) | (kcol + 1); }
            if (c2 >= tau_b) { float s = c2 * 0.125f; int p = atomicAdd(&cnt[ar + 8], 1); if (p < CAP) candRowB[p] = ((unsigned)f2s16(s) << 16) | kcol; }
            if (c3 >= tau_b) { float s = c3 * 0.125f; int p = atomicAdd(&cnt[ar + 8], 1); if (p < CAP) candRowB[p] = ((unsigned)f2s16(s) << 16) | (kcol + 1); }
        }
        __syncthreads();
    }
    // mainloop done; Kbf region is dead -> overlay selection arrays

    unsigned* pkA = (unsigned*)(smem + OFF_PK);
    unsigned short* idsA = (unsigned short*)(smem + OFF_IDS);
    unsigned long long* skA = (unsigned long long*)(smem + OFF_SKEY);

    for (int rr = 0; rr < 4; ++rr) {
        const int row  = w * 4 + rr;
        const int grow = rowBase + row;
        const float* qrow = Qs + row * 68;
        unsigned* pk = pkA + row * CAP;
        unsigned short* ids = idsA + row * TRIM;
        unsigned long long* skey = skA + row * TRIM;

        int n = cnt[row];
        const bool fb = (n < MINC || n > CAP);

        if (!fb) {
            const unsigned* candRow = g_cand + (size_t)grow * CAPG;
            for (int i = lane; i < n; i += 32) pk[i] = candRow[i];
        } else {
            // rare fallback: bisection threshold over recomputed fp32 scores
            float nx = qrow[lane], ny = qrow[lane + 32];
            float nrm = nx * nx + ny * ny;
            #pragma unroll
            for (int o = 16; o >= 1; o >>= 1) nrm += __shfl_xor_sync(full, nrm, o);
            unsigned lo = 0u, hi = 0xFFFFFFFFu;
            unsigned mid = f2sortable(Z_TAU * sqrtf(nrm) * 0.125f), tu = 0u;
            bool have = false;
            for (int it = 0; it < 34; ++it) {
                int c = 0;
                for (int j = 0; j < 64; ++j) {
                    const float4* k4 = (const float4*)(kb + (size_t)(j * 32 + lane) * D_);
                    float s = 0.0f;
                    #pragma unroll
                    for (int dg = 0; dg < 16; ++dg) {
                        float4 kv = k4[dg];
                        s = fmaf(qrow[dg * 4],     kv.x, s);
                        s = fmaf(qrow[dg * 4 + 1], kv.y, s);
                        s = fmaf(qrow[dg * 4 + 2], kv.z, s);
                        s = fmaf(qrow[dg * 4 + 3], kv.w, s);
                    }
                    c += (f2sortable(s * 0.125f) >= mid);
                }
                #pragma unroll
                for (int o = 16; o >= 1; o >>= 1) c += __shfl_xor_sync(full, c, o);
                if (c >= MINC && c <= CAP) { tu = mid; have = true; break; }
                if (c < MINC) hi = mid; else { lo = mid; tu = mid; have = true; }
                mid = lo + ((hi - lo) >> 1);
                if (mid == lo) { if (!have) tu = lo; break; }
            }
            int base = 0;
            for (int j = 0; j < 64; ++j) {
                int key = j * 32 + lane;
                const float4* k4 = (const float4*)(kb + (size_t)key * D_);
                float s = 0.0f;
                #pragma unroll
                for (int dg = 0; dg < 16; ++dg) {
                    float4 kv = k4[dg];
                    s = fmaf(qrow[dg * 4],     kv.x, s);
                    s = fmaf(qrow[dg * 4 + 1], kv.y, s);
                    s = fmaf(qrow[dg * 4 + 2], kv.z, s);
                    s = fmaf(qrow[dg * 4 + 3], kv.w, s);
                }
                s *= 0.125f;
                bool cnd = f2sortable(s) >= tu;
                unsigned mk = __ballot_sync(full, cnd);
                if (cnd) {
                    int pos = base + __popc(mk & ltmask);
                    if (pos < CAP) pk[pos] = ((unsigned)f2s16(s) << 16) | (unsigned)key;
                }
                base += __popc(mk);
            }
            n = base < CAP ? base : CAP;
        }
        __syncwarp();

        // ---- trim: keep packed-rank < TRIM (3-wide fast path for n<=96) ----
        unsigned mp[5];
        int mc = 0;
        for (int i = lane; i < n; i += 32) mp[mc++] = pk[i];
        int rk[5] = {0, 0, 0, 0, 0};
        if (n <= 96) {
            for (int j = 0; j < n; ++j) {
                unsigned pj = pk[j];
                rk[0] += (pj > mp[0]);
                rk[1] += (pj > mp[1]);
                rk[2] += (pj > mp[2]);
            }
        } else {
            for (int j = 0; j < n; ++j) {
                unsigned pj = pk[j];
                #pragma unroll
                for (int c = 0; c < 5; ++c) rk[c] += (pj > mp[c]);
            }
        }
        int base2 = 0;
        #pragma unroll
        for (int c = 0; c < 5; ++c) {
            bool sv = (c < mc) && (rk[c] < TRIM);
            unsigned msk = __ballot_sync(full, sv);
            if (sv) {
                int pos = base2 + __popc(msk & ltmask);
                ids[pos] = (unsigned short)(mp[c] & 0xFFFFu);
            }
            base2 += __popc(msk);
        }
        const int m = base2;                 // = min(n, TRIM) <= 40
        __syncwarp();

        // ---- cooperative fp32 rescore: 4-lane groups, full 32B sectors ----
        const int g4 = lane >> 2, l4 = lane & 3;
        for (int i = 0; i < m; i += 8) {
            int slot = i + g4;
            float s = 0.0f;
            int idx = 0;
            if (slot < m) {
                idx = ids[slot];
                const float4* kr = (const float4*)(kb + (size_t)idx * D_);
                #pragma unroll
                for (int j = 0; j < 4; ++j) {
                    float4 kv = kr[l4 + j * 4];
                    const float* qq = qrow + l4 * 4 + j * 16;
                    s = fmaf(qq[0], kv.x, s); s = fmaf(qq[1], kv.y, s);
                    s = fmaf(qq[2], kv.z, s); s = fmaf(qq[3], kv.w, s);
                }
            }
            s += __shfl_xor_sync(full, s, 1);
            s += __shfl_xor_sync(full, s, 2);
            if (slot < m && l4 == 0) {
                s *= 0.125f;
                skey[slot] = ((unsigned long long)f2sortable(s) << 32)
                           | (unsigned)(2047 - idx);
            }
        }
        __syncwarp();

        // ---- exact top-32 among m (u64: val desc, tie -> lower idx) ----
        float* selv = (float*)pk;            // reuse pk row area (trim done)
        int*   seli = (int*)(pk + 32);
        unsigned long long fk[2] = {0ull, 0ull};
        int mc2 = 0;
        for (int i = lane; i < m; i += 32) fk[mc2++] = skey[i];
        int rk2[2] = {0, 0};
        for (int j = 0; j < m; ++j) {
            unsigned long long kj = skey[j];
            rk2[0] += (kj > fk[0]);
            rk2[1] += (kj > fk[1]);
        }
        #pragma unroll
        for (int c = 0; c < 2; ++c) {
            if (c < mc2 && rk2[c] < TOPK_) {
                seli[rk2[c]] = 2047 - (int)(fk[c] & 0xFFFFFFFFull);
                selv[rk2[c]] = s2f((unsigned)(fk[c] >> 32));
            }
        }
        __syncwarp();

        // ---- output ----
        float a0 = 0.0f, a1 = 0.0f;
        #pragma unroll
        for (int j = 0; j < TOPK_; ++j) {
            float vv = selv[j];
            const float* vrow = vb + (size_t)seli[j] * D_;
            a0 = fmaf(vv, vrow[lane], a0);
            a1 = fmaf(vv, vrow[lane + 32], a1);
        }
        out[(size_t)grow * D_ + lane]      = a0;
        out[(size_t)grow * D_ + lane + 32] = a1;
        __syncwarp();
    }
}

// ---------------------------------------------------------------------------
extern "C" void kernel_launch(void* const* d_in, const int* in_sizes, int n_in,
                              void* d_out, int out_size)
{
    const float* q = (const float*)d_in[0];
    const float* k = (const float*)d_in[1];
    const float* v = (const float*)d_in[2];
    float* out = (float*)d_out;

    convert_k<<<(B_ * L_ * 8) / 256, 256>>>(k);

    cudaFuncSetAttribute(fused_attn,
                         cudaFuncAttributeMaxDynamicSharedMemorySize, SMEM_A);
    fused_attn<<<NBLK, 256, SMEM_A>>>(q, k, v, out);
}

// round 16
// speedup vs baseline: 1.7200x; 1.0754x over previous
#include <cuda_runtime.h>
#include <cuda_bf16.h>
#include <cstdint>

// Problem constants
#define B_    8
#define L_    2048
#define D_    64
#define TOPK_ 32

// Tiling
#define TQ     32
#define CK     128
#define NCHUNK (L_ / CK)         // 16
#define NBLK   (B_ * L_ / TQ)    // 512
#define BPB    (L_ / TQ)         // 64

// Selection: analytic threshold tau = Z_TAU * ||q|| / 8
#define Z_TAU 1.70f
#define MINC  40
#define CAP   144
#define CAPG  160
#define TRIM  40

#define KST  72                  // K row stride (bf16 elems) = 144B pitch
#define CHUNK_BYTES (CK * KST * 2)   // 18432 bytes per chunk tile

// ---- dynamic smem layout (bytes) ----
#define OFF_KBF   0              // bf16 [2][128][72] = 36864  (overlaid post-loop)
#define OFF_QS    36864          // f32  [32][68]     =  8704
#define OFF_TAU   45568          // f32  [32]  (stores tau*8 = Z*||q||)
#define OFF_CNT   45696          // int  [32]
#define OFF_MBAR  45824          // u64  [2]
#define SMEM_A    45952          // x4 blocks/SM = 183808 <= 228KB

// selection overlays on the KBF region (valid only after mainloop)
#define OFF_PK    0              // u32 [32][144] = 18432 (also selv/seli per row)
#define OFF_IDS   18432          // u16 [32][40]  =  2560
#define OFF_SKEY  20992          // u64 [32][40]  = 10240

// Global scratch. gKbf is CHUNK-PADDED + per-row PERMUTED:
//   addr(b, ck, keyIn, i) = ((b*16 + ck)*128 + keyIn)*72 + i
//   elem i = ac_g*16 + ks*4 + j  <->  input d = ks*16 + 2*ac_g + (j&1) + (j>=2)*8
// Each 18432-byte chunk tile is contiguous => single cp.async.bulk per chunk,
// and the smem tile is byte-identical to the global tile (same 72-elem pitch).
__device__ __nv_bfloat16 gKbf[(size_t)B_ * NCHUNK * CK * KST];   // 2.25 MB
__device__ unsigned g_cand[(size_t)B_ * L_ * CAPG];              // packed (s16<<16)|idx

__device__ __forceinline__ unsigned f2sortable(float f) {
    unsigned bb = __float_as_uint(f);
    return (bb & 0x80000000u) ? ~bb : (bb | 0x80000000u);
}
__device__ __forceinline__ float s2f(unsigned u) {
    unsigned bb = (u & 0x80000000u) ? (u & 0x7FFFFFFFu) : ~u;
    return __uint_as_float(bb);
}
__device__ __forceinline__ unsigned short f2s16(float f) {
    unsigned short b = __bfloat16_as_ushort(__float2bfloat16(f));
    return (b & 0x8000) ? (unsigned short)~b : (unsigned short)(b | 0x8000);
}
__device__ __forceinline__ uint32_t pack_bf2(float lo, float hi) {
    __nv_bfloat162 h2 = __floats2bfloat162_rn(lo, hi);
    return *reinterpret_cast<uint32_t*>(&h2);
}

__device__ __forceinline__ void mma_bf16(
    float& c0, float& c1, float& c2, float& c3,
    uint32_t a0, uint32_t a1, uint32_t a2, uint32_t a3,
    uint32_t b0, uint32_t b1)
{
    asm volatile(
        "mma.sync.aligned.m16n8k16.row.col.f32.bf16.bf16.f32 "
        "{%0,%1,%2,%3}, {%4,%5,%6,%7}, {%8,%9}, {%0,%1,%2,%3};\n"
        : "+f"(c0), "+f"(c1), "+f"(c2), "+f"(c3)
        : "r"(a0), "r"(a1), "r"(a2), "r"(a3), "r"(b0), "r"(b1));
}

// ---- bulk-copy + mbarrier helpers ----
__device__ __forceinline__ void mbar_init(uint32_t mbar, uint32_t count) {
    asm volatile("mbarrier.init.shared.b64 [%0], %1;" :: "r"(mbar), "r"(count) : "memory");
}
__device__ __forceinline__ void mbar_expect_tx(uint32_t mbar, uint32_t bytes) {
    asm volatile("mbarrier.arrive.expect_tx.shared.b64 _, [%0], %1;"
                 :: "r"(mbar), "r"(bytes) : "memory");
}
__device__ __forceinline__ void bulk_g2s(uint32_t smem_dst, const void* gsrc,
                                         uint32_t bytes, uint32_t mbar) {
    asm volatile(
        "cp.async.bulk.shared::cta.global.mbarrier::complete_tx::bytes "
        "[%0], [%1], %2, [%3];"
        :: "r"(smem_dst), "l"(gsrc), "r"(bytes), "r"(mbar) : "memory");
}
__device__ __forceinline__ void mbar_wait(uint32_t mbar, uint32_t parity) {
    asm volatile(
        "{\n\t"
        ".reg .pred P;\n\t"
        "WAIT_%=: \n\t"
        "mbarrier.try_wait.parity.acquire.cta.shared::cta.b64 P, [%0], %1, 0x989680;\n\t"
        "@!P bra WAIT_%=;\n\t"
        "}"
        :: "r"(mbar), "r"(parity) : "memory");
}

// ---------------------------------------------------------------------------
// Kernel 0: K fp32 -> bf16, chunk-padded + permuted (see gKbf comment)
// grid: B_*L_*8/256 = 512 blocks; thread handles one 8-elem output segment
// ---------------------------------------------------------------------------
__global__ __launch_bounds__(256) void convert_k(const float* __restrict__ k) {
    int idx = blockIdx.x * 256 + threadIdx.x;
    int r   = idx >> 3;              // global key row 0..16383
    int seg = idx & 7;
    const float* kr = k + (size_t)r * D_;
    int acg = seg >> 1;              // 0..3
    int ks0 = (seg & 1) * 2;         // ks pair base: 0 or 2
    int ac  = acg * 2;

    uint4 o;
    {
        int base = ks0 * 16 + ac;
        o.x = pack_bf2(kr[base],     kr[base + 1]);
        o.y = pack_bf2(kr[base + 8], kr[base + 9]);
    }
    {
        int base = (ks0 + 1) * 16 + ac;
        o.z = pack_bf2(kr[base],     kr[base + 1]);
        o.w = pack_bf2(kr[base + 8], kr[base + 9]);
    }
    // chunk-padded address: ((b*16 + ck)*128 + keyIn)*72 + acg*16 + ks0*4
    int b     = r >> 11;
    int kk    = r & 2047;
    int ck    = kk >> 7;
    int keyIn = kk & 127;
    size_t rowBaseE = ((size_t)(b * NCHUNK + ck) * CK + keyIn) * KST;
    *(uint4*)((unsigned short*)gKbf + rowBaseE + seg * 8) = o;
}

// ---------------------------------------------------------------------------
// Fused: HMMA score + threshold harvest + trim + rescore + top-32 + output
// K staged per chunk by ONE cp.async.bulk (18432 B) on an mbarrier.
// ---------------------------------------------------------------------------
__global__ __launch_bounds__(256, 4) void fused_attn(
    const float* __restrict__ q, const float* __restrict__ k,
    const float* __restrict__ v, float* __restrict__ out)
{
    extern __shared__ __align__(16) char smem[];
    unsigned short* Kbf = (unsigned short*)(smem + OFF_KBF);
    float* Qs   = (float*)(smem + OFF_QS);
    float* tauA = (float*)(smem + OFF_TAU);   // tau*8 = Z*||q||
    int*   cnt  = (int*)(smem + OFF_CNT);

    const int t    = threadIdx.x;
    const int lane = t & 31;
    const int w    = t >> 5;
    const unsigned full = 0xffffffffu;
    const unsigned ltmask = (1u << lane) - 1u;

    const int rowBase = blockIdx.x * TQ;
    const int b       = blockIdx.x / BPB;
    const float* kb   = k + (size_t)b * L_ * D_;
    const float* vb   = v + (size_t)b * L_ * D_;
    const __nv_bfloat16* gkb = gKbf + (size_t)b * NCHUNK * CK * KST;
    const uint32_t ksBase = (uint32_t)__cvta_generic_to_shared(Kbf);
    const uint32_t mbar0  = (uint32_t)__cvta_generic_to_shared(smem + OFF_MBAR);

    for (int i = t; i < TQ * 16; i += 256) {
        int row = i >> 4, dg4 = (i & 15) << 2;
        *(float4*)(Qs + row * 68 + dg4) =
            *(const float4*)(q + ((size_t)(rowBase + row)) * D_ + dg4);
    }
    if (t < TQ) cnt[t] = 0;
    if (t == 0) { mbar_init(mbar0, 1); mbar_init(mbar0 + 8, 1); }
    __syncthreads();

    // per-row analytic tau*8 (warp w -> rows 4w..4w+3)
    for (int rr = 0; rr < 4; ++rr) {
        int row = w * 4 + rr;
        float x = Qs[row * 68 + lane], y = Qs[row * 68 + lane + 32];
        float nrm = x * x + y * y;
        #pragma unroll
        for (int o = 16; o >= 1; o >>= 1) nrm += __shfl_xor_sync(full, nrm, o);
        if (lane == 0) tauA[row] = Z_TAU * sqrtf(nrm);    // raw-score threshold
    }

    // A fragments (Q) once
    const int rg = w >> 2;
    const int ns = w & 3;
    const int qr = lane >> 2;
    const int acg = lane & 3;
    const int ar = rg * 16 + qr;
    const int ac = acg * 2;
    uint32_t afr[4][4];
    #pragma unroll
    for (int ks = 0; ks < 4; ++ks) {
        int col = ks * 16 + ac;
        afr[ks][0] = pack_bf2(Qs[ar * 68 + col],           Qs[ar * 68 + col + 1]);
        afr[ks][1] = pack_bf2(Qs[(ar + 8) * 68 + col],     Qs[(ar + 8) * 68 + col + 1]);
        afr[ks][2] = pack_bf2(Qs[ar * 68 + col + 8],       Qs[ar * 68 + col + 9]);
        afr[ks][3] = pack_bf2(Qs[(ar + 8) * 68 + col + 8], Qs[(ar + 8) * 68 + col + 9]);
    }

    // prologue: bulk-copy chunk 0 into buffer 0
    if (t == 0) {
        mbar_expect_tx(mbar0, CHUNK_BYTES);
        bulk_g2s(ksBase, gkb, CHUNK_BYTES, mbar0);
    }

    unsigned* candRowA = g_cand + (size_t)(rowBase + ar) * CAPG;
    unsigned* candRowB = g_cand + (size_t)(rowBase + ar + 8) * CAPG;
    __syncthreads();                        // tau + cnt visible before epilogue

    const float tau_a = tauA[ar], tau_b = tauA[ar + 8];   // hoisted (loop-invariant)

    for (int chunk = 0; chunk < NCHUNK; ++chunk) {
        // stage next chunk into the other buffer (freed by prev-iter syncthreads)
        if (chunk + 1 < NCHUNK && t == 0) {
            const int nb = (chunk + 1) & 1;
            mbar_expect_tx(mbar0 + nb * 8, CHUNK_BYTES);
            bulk_g2s(ksBase + nb * CHUNK_BYTES,
                     gkb + (size_t)(chunk + 1) * CK * KST,
                     CHUNK_BYTES, mbar0 + nb * 8);
        }
        // wait for current chunk's tile
        mbar_wait(mbar0 + (chunk & 1) * 8, (chunk >> 1) & 1);

        const unsigned short* Kb = Kbf + (chunk & 1) * (CK * KST);
        #pragma unroll
        for (int nt = 0; nt < 4; ++nt) {
            const int keyInChunk = ns * 32 + nt * 8 + qr;
            const uint4* bp = (const uint4*)&Kb[keyInChunk * KST + acg * 16];
            uint4 bA = bp[0];
            uint4 bB = bp[1];
            float c0 = 0.f, c1 = 0.f, c2 = 0.f, c3 = 0.f;
            mma_bf16(c0, c1, c2, c3, afr[0][0], afr[0][1], afr[0][2], afr[0][3], bA.x, bA.y);
            mma_bf16(c0, c1, c2, c3, afr[1][0], afr[1][1], afr[1][2], afr[1][3], bA.z, bA.w);
            mma_bf16(c0, c1, c2, c3, afr[2][0], afr[2][1], afr[2][2], afr[2][3], bB.x, bB.y);
            mma_bf16(c0, c1, c2, c3, afr[3][0], afr[3][1], afr[3][2], afr[3][3], bB.z, bB.w);
            const unsigned kcol = chunk * CK + ns * 32 + nt * 8 + ac;
            if (c0 >= tau_a) { float s = c0 * 0.125f; int p = atomicAdd(&cnt[ar], 1);     if (p < CAP) candRowA[p] = ((unsigned)f2s16(s) << 16) | kcol; }
            if (c1 >= tau_a) { float s = c1 * 0.125f; int p = atomicAdd(&cnt[ar], 1);     if (p < CAP) candRowA[p] = ((unsigned)f2s16(s) << 16) | (kcol + 1); }
            if (c2 >= tau_b) { float s = c2 * 0.125f; int p = atomicAdd(&cnt[ar + 8], 1); if (p < CAP) candRowB[p] = ((unsigned)f2s16(s) << 16) | kcol; }
            if (c3 >= tau_b) { float s = c3 * 0.125f; int p = atomicAdd(&cnt[ar + 8], 1); if (p < CAP) candRowB[p] = ((unsigned)f2s16(s) << 16) | (kcol + 1); }
        }
        __syncthreads();   // all reads of this buffer done before re-arm/overwrite
    }
    // mainloop done; Kbf region is dead -> overlay selection arrays

    unsigned* pkA = (unsigned*)(smem + OFF_PK);
    unsigned short* idsA = (unsigned short*)(smem + OFF_IDS);
    unsigned long long* skA = (unsigned long long*)(smem + OFF_SKEY);

    for (int rr = 0; rr < 4; ++rr) {
        const int row  = w * 4 + rr;
        const int grow = rowBase + row;
        const float* qrow = Qs + row * 68;
        unsigned* pk = pkA + row * CAP;
        unsigned short* ids = idsA + row * TRIM;
        unsigned long long* skey = skA + row * TRIM;

        int n = cnt[row];
        const bool fb = (n < MINC || n > CAP);

        if (!fb) {
            const unsigned* candRow = g_cand + (size_t)grow * CAPG;
            for (int i = lane; i < n; i += 32) pk[i] = candRow[i];
        } else {
            // rare fallback: bisection threshold over recomputed fp32 scores
            float nx = qrow[lane], ny = qrow[lane + 32];
            float nrm = nx * nx + ny * ny;
            #pragma unroll
            for (int o = 16; o >= 1; o >>= 1) nrm += __shfl_xor_sync(full, nrm, o);
            unsigned lo = 0u, hi = 0xFFFFFFFFu;
            unsigned mid = f2sortable(Z_TAU * sqrtf(nrm) * 0.125f), tu = 0u;
            bool have = false;
            for (int it = 0; it < 34; ++it) {
                int c = 0;
                for (int j = 0; j < 64; ++j) {
                    const float4* k4 = (const float4*)(kb + (size_t)(j * 32 + lane) * D_);
                    float s = 0.0f;
                    #pragma unroll
                    for (int dg = 0; dg < 16; ++dg) {
                        float4 kv = k4[dg];
                        s = fmaf(qrow[dg * 4],     kv.x, s);
                        s = fmaf(qrow[dg * 4 + 1], kv.y, s);
                        s = fmaf(qrow[dg * 4 + 2], kv.z, s);
                        s = fmaf(qrow[dg * 4 + 3], kv.w, s);
                    }
                    c += (f2sortable(s * 0.125f) >= mid);
                }
                #pragma unroll
                for (int o = 16; o >= 1; o >>= 1) c += __shfl_xor_sync(full, c, o);
                if (c >= MINC && c <= CAP) { tu = mid; have = true; break; }
                if (c < MINC) hi = mid; else { lo = mid; tu = mid; have = true; }
                mid = lo + ((hi - lo) >> 1);
                if (mid == lo) { if (!have) tu = lo; break; }
            }
            int base = 0;
            for (int j = 0; j < 64; ++j) {
                int key = j * 32 + lane;
                const float4* k4 = (const float4*)(kb + (size_t)key * D_);
                float s = 0.0f;
                #pragma unroll
                for (int dg = 0; dg < 16; ++dg) {
                    float4 kv = k4[dg];
                    s = fmaf(qrow[dg * 4],     kv.x, s);
                    s = fmaf(qrow[dg * 4 + 1], kv.y, s);
                    s = fmaf(qrow[dg * 4 + 2], kv.z, s);
                    s = fmaf(qrow[dg * 4 + 3], kv.w, s);
                }
                s *= 0.125f;
                bool cnd = f2sortable(s) >= tu;
                unsigned mk = __ballot_sync(full, cnd);
                if (cnd) {
                    int pos = base + __popc(mk & ltmask);
                    if (pos < CAP) pk[pos] = ((unsigned)f2s16(s) << 16) | (unsigned)key;
                }
                base += __popc(mk);
            }
            n = base < CAP ? base : CAP;
        }
        __syncwarp();

        // ---- trim: keep packed-rank < TRIM (3-wide fast path for n<=96) ----
        unsigned mp[5];
        int mc = 0;
        for (int i = lane; i < n; i += 32) mp[mc++] = pk[i];
        int rk[5] = {0, 0, 0, 0, 0};
        if (n <= 96) {
            for (int j = 0; j < n; ++j) {
                unsigned pj = pk[j];
                rk[0] += (pj > mp[0]);
                rk[1] += (pj > mp[1]);
                rk[2] += (pj > mp[2]);
            }
        } else {
            for (int j = 0; j < n; ++j) {
                unsigned pj = pk[j];
                #pragma unroll
                for (int c = 0; c < 5; ++c) rk[c] += (pj > mp[c]);
            }
        }
        int base2 = 0;
        #pragma unroll
        for (int c = 0; c < 5; ++c) {
            bool sv = (c < mc) && (rk[c] < TRIM);
            unsigned msk = __ballot_sync(full, sv);
            if (sv) {
                int pos = base2 + __popc(msk & ltmask);
                ids[pos] = (unsigned short)(mp[c] & 0xFFFFu);
            }
            base2 += __popc(msk);
        }
        const int m = base2;                 // = min(n, TRIM) <= 40
        __syncwarp();

        // ---- cooperative fp32 rescore: 4-lane groups, full 32B sectors ----
        const int g4 = lane >> 2, l4 = lane & 3;
        for (int i = 0; i < m; i += 8) {
            int slot = i + g4;
            float s = 0.0f;
            int idx = 0;
            if (slot < m) {
                idx = ids[slot];
                const float4* kr = (const float4*)(kb + (size_t)idx * D_);
                #pragma unroll
                for (int j = 0; j < 4; ++j) {
                    float4 kv = kr[l4 + j * 4];
                    const float* qq = qrow + l4 * 4 + j * 16;
                    s = fmaf(qq[0], kv.x, s); s = fmaf(qq[1], kv.y, s);
                    s = fmaf(qq[2], kv.z, s); s = fmaf(qq[3], kv.w, s);
                }
            }
            s += __shfl_xor_sync(full, s, 1);
            s += __shfl_xor_sync(full, s, 2);
            if (slot < m && l4 == 0) {
                s *= 0.125f;
                skey[slot] = ((unsigned long long)f2sortable(s) << 32)
                           | (unsigned)(2047 - idx);
            }
        }
        __syncwarp();

        // ---- exact top-32 among m (u64: val desc, tie -> lower idx) ----
        float* selv = (float*)pk;            // reuse pk row area (trim done)
        int*   seli = (int*)(pk + 32);
        unsigned long long fk[2] = {0ull, 0ull};
        int mc2 = 0;
        for (int i = lane; i < m; i += 32) fk[mc2++] = skey[i];
        int rk2[2] = {0, 0};
        for (int j = 0; j < m; ++j) {
            unsigned long long kj = skey[j];
            rk2[0] += (kj > fk[0]);
            rk2[1] += (kj > fk[1]);
        }
        #pragma unroll
        for (int c = 0; c < 2; ++c) {
            if (c < mc2 && rk2[c] < TOPK_) {
                seli[rk2[c]] = 2047 - (int)(fk[c] & 0xFFFFFFFFull);
                selv[rk2[c]] = s2f((unsigned)(fk[c] >> 32));
            }
        }
        __syncwarp();

        // ---- output ----
        float a0 = 0.0f, a1 = 0.0f;
        #pragma unroll
        for (int j = 0; j < TOPK_; ++j) {
            float vv = selv[j];
            const float* vrow = vb + (size_t)seli[j] * D_;
            a0 = fmaf(vv, vrow[lane], a0);
            a1 = fmaf(vv, vrow[lane + 32], a1);
        }
        out[(size_t)grow * D_ + lane]      = a0;
        out[(size_t)grow * D_ + lane + 32] = a1;
        __syncwarp();
    }
}

// ---------------------------------------------------------------------------
extern "C" void kernel_launch(void* const* d_in, const int* in_sizes, int n_in,
                              void* d_out, int out_size)
{
    const float* q = (const float*)d_in[0];
    const float* k = (const float*)d_in[1];
    const float* v = (const float*)d_in[2];
    float* out = (float*)d_out;

    convert_k<<<(B_ * L_ * 8) / 256, 256>>>(k);

    cudaFuncSetAttribute(fused_attn,
                         cudaFuncAttributeMaxDynamicSharedMemorySize, SMEM_A);
    fused_attn<<<NBLK, 256, SMEM_A>>>(q, k, v, out);
}